// round 4
// baseline (speedup 1.0000x reference)
#include <cuda_runtime.h>
#include <math.h>

#define B_  4
#define Nn  384
#define E_  768
#define H_  32
#define F_  3072
#define L_  12
#define S_  512
#define D_  24
#define T_  (B_*Nn)          // 1536 tokens
#define QKV 2304             // 3*E

// -------------------- scratch (static device allocations) --------------------
__device__ float g_x   [T_*E_];
__device__ float g_q   [T_*E_];
__device__ float g_k   [T_*E_];
__device__ float g_h   [T_*F_];      // holds QKV output (T x 2304), then FFN hidden
__device__ float g_bias[B_*H_*Nn*Nn];
__device__ float g_sc  [B_*H_*Nn*Nn];
__device__ float g_wqkv[L_*E_*QKV];  // packed [l][k][3E]
__device__ float g_bqkv[L_*QKV];

// -------------------- weight packing (per launch, deterministic) -------------
__global__ void packw_k(const float* __restrict__ Wq, const float* __restrict__ Wk,
                        const float* __restrict__ Wv, float* __restrict__ wo) {
    long idx = (long)blockIdx.x * blockDim.x + threadIdx.x;
    if (idx >= (long)L_*E_*QKV) return;
    int n = (int)(idx % QKV); long r = idx / QKV;
    int k = (int)(r % E_);    int l = (int)(r / E_);
    size_t base = ((size_t)l*E_ + k) * E_;
    float v;
    if      (n < E_)   v = Wq[base + n];
    else if (n < 2*E_) v = Wk[base + n - E_];
    else               v = Wv[base + n - 2*E_];
    wo[idx] = v;
}
__global__ void packb_k(const float* __restrict__ bq, const float* __restrict__ bk,
                        const float* __restrict__ bv, float* __restrict__ bo) {
    int idx = blockIdx.x * blockDim.x + threadIdx.x;
    if (idx >= L_*QKV) return;
    int n = idx % QKV, l = idx / QKV;
    float v;
    if      (n < E_)   v = bq[l*E_ + n];
    else if (n < 2*E_) v = bk[l*E_ + n - E_];
    else               v = bv[l*E_ + n - 2*E_];
    bo[idx] = v;
}

// -------------------- embedding: x[n*B+b][e] --------------------
__global__ void embed_k(const int* __restrict__ nt, const float* __restrict__ nif,
                        const int* __restrict__ ind, const int* __restrict__ outd,
                        const float* __restrict__ nemb, const float* __restrict__ iemb,
                        const float* __restrict__ oemb, float* __restrict__ x) {
    int idx = blockIdx.x * blockDim.x + threadIdx.x;
    if (idx >= T_*E_) return;
    int e = idx % E_, tok = idx / E_;
    int b = tok % B_, n = tok / B_;
    int bn = b*Nn + n;
    int t  = nt[bn];
    x[idx] = nemb[t*E_+e] + iemb[ind[bn]*E_+e] + oemb[outd[bn]*E_+e] + nif[(size_t)bn*E_+e];
}

// -------------------- spatial bias: bias[b,h,n,m] --------------------
__global__ void bias_k(const int* __restrict__ sp, const float* __restrict__ ab,
                       const float* __restrict__ se, const float* __restrict__ ser,
                       float* __restrict__ bias) {
    long idx = (long)blockIdx.x * blockDim.x + threadIdx.x;
    if (idx >= (long)B_*H_*Nn*Nn) return;
    int m = (int)(idx % Nn); long r = idx / Nn;
    int n = (int)(r % Nn);   r /= Nn;
    int h = (int)(r % H_);
    int b = (int)(r / H_);
    int s1 = sp[(b*Nn+n)*Nn + m];
    int s2 = sp[(b*Nn+m)*Nn + n];
    bias[idx] = se[s1*H_+h] + ser[s2*H_+h] + ab[(b*Nn+n)*Nn + m];
}

__device__ __forceinline__ float gelu_f(float x) {
    return 0.5f * x * (1.0f + tanhf(0.7978845608028654f * (x + 0.044715f * x * x * x)));
}

// -------------------- cp.async helpers --------------------
__device__ __forceinline__ unsigned sptr(const void* p) {
    return (unsigned)__cvta_generic_to_shared(p);
}
#define CP_ASYNC16(dst, src) \
    asm volatile("cp.async.cg.shared.global [%0], [%1], 16;\n" :: "r"(dst), "l"(src) : "memory")
#define CP_COMMIT() asm volatile("cp.async.commit_group;\n" ::: "memory")
#define CP_WAIT1()  asm volatile("cp.async.wait_group 1;\n" ::: "memory")

// exact split: hi = low-13-bits-masked (exact tf32), lo = a - hi (exact)
__device__ __forceinline__ void split_tf32(float a, unsigned& hi, unsigned& lo) {
    unsigned u = __float_as_uint(a) & 0xffffe000u;
    hi = u;
    lo = __float_as_uint(a - __uint_as_float(u));
}

#define MMA_TF32(acc, a0,a1,a2,a3, b0,b1) \
    asm volatile("mma.sync.aligned.m16n8k8.row.col.f32.tf32.tf32.f32 " \
                 "{%0,%1,%2,%3}, {%4,%5,%6,%7}, {%8,%9}, {%0,%1,%2,%3};" \
                 : "+f"(acc[0]), "+f"(acc[1]), "+f"(acc[2]), "+f"(acc[3]) \
                 : "r"(a0), "r"(a1), "r"(a2), "r"(a3), "r"(b0), "r"(b1))

// -------------------- tensor-core GEMM, 3xTF32 (fp32-accurate) --------------
// C[M,Nc] = epi((A[M,K]@W[K,Nc] + bias) * scale)
// Block 128x64, BK=16, 8 warps (4m x 2n), warp tile 32x32, cp.async 3-stage.
#define BM 128
#define BN 64
#define BKK 16

template<int EPI>  // 0 = bias(+scale), 1 = bias + gelu
__global__ void __launch_bounds__(256, 2)
tgemm_k(const float* __restrict__ A, const float* __restrict__ W,
        const float* __restrict__ bias, float* __restrict__ C,
        int M, int K, int Nc, float scale) {
    __shared__ float As[3][BM][20];    // raw fp32, [m][k], stride 20 (conflict-free)
    __shared__ float Bs[3][BKK][BN];   // [k][n], col swizzled: n ^ (8*(k&3))

    int tid  = threadIdx.x;
    int wid  = tid >> 5, lane = tid & 31;
    int g    = lane >> 2;
    int qq   = lane & 3;
    int wm   = (wid & 3) * 32;
    int wn   = (wid >> 2) * 32;
    int bm0  = blockIdx.y * BM;
    int bn0  = blockIdx.x * BN;

    int am = tid >> 1;
    int ak = (tid & 1) * 8;
    int bk = tid >> 4;
    int bn = (tid & 15) * 4;
    const float* Ap = A + (size_t)(bm0 + am) * K + ak;
    const float* Wp = W + (size_t)bk * Nc + bn0 + bn;
    int sn = bn ^ (8 * (bk & 3));

    float acc[2][4][4];
#pragma unroll
    for (int i = 0; i < 2; i++)
#pragma unroll
        for (int j = 0; j < 4; j++)
#pragma unroll
            for (int c = 0; c < 4; c++) acc[i][j][c] = 0.f;

    int ntiles = K / BKK;
    // prologue: stages 0,1
#pragma unroll
    for (int p = 0; p < 2; p++) {
        unsigned da = sptr(&As[p][am][ak]);
        CP_ASYNC16(da,      Ap + p*BKK);
        CP_ASYNC16(da + 16, Ap + p*BKK + 4);
        unsigned db = sptr(&Bs[p][bk][sn]);
        CP_ASYNC16(db, Wp + (size_t)p*BKK*Nc);
        CP_COMMIT();
    }

    for (int t = 0; t < ntiles; t++) {
        CP_WAIT1();
        __syncthreads();
        int tn = t + 2;
        if (tn < ntiles) {
            int s2 = tn % 3;
            unsigned da = sptr(&As[s2][am][ak]);
            CP_ASYNC16(da,      Ap + (size_t)tn*BKK);
            CP_ASYNC16(da + 16, Ap + (size_t)tn*BKK + 4);
            unsigned db = sptr(&Bs[s2][bk][sn]);
            CP_ASYNC16(db, Wp + (size_t)tn*BKK*Nc);
        }
        CP_COMMIT();

        int s = t % 3;
#pragma unroll
        for (int kk = 0; kk < 2; kk++) {
            int k0 = kk * 8;
            unsigned ah[2][4], al[2][4], bh[4][2], bl[4][2];
#pragma unroll
            for (int mt = 0; mt < 2; mt++) {
                int mr = wm + mt * 16;
                float r0 = As[s][mr + g    ][k0 + qq];
                float r1 = As[s][mr + g + 8][k0 + qq];
                float r2 = As[s][mr + g    ][k0 + qq + 4];
                float r3 = As[s][mr + g + 8][k0 + qq + 4];
                split_tf32(r0, ah[mt][0], al[mt][0]);
                split_tf32(r1, ah[mt][1], al[mt][1]);
                split_tf32(r2, ah[mt][2], al[mt][2]);
                split_tf32(r3, ah[mt][3], al[mt][3]);
            }
#pragma unroll
            for (int nt2 = 0; nt2 < 4; nt2++) {
                int nc = (wn + nt2 * 8 + g) ^ (8 * qq);
                float s0 = Bs[s][k0 + qq    ][nc];
                float s1 = Bs[s][k0 + qq + 4][nc];
                split_tf32(s0, bh[nt2][0], bl[nt2][0]);
                split_tf32(s1, bh[nt2][1], bl[nt2][1]);
            }
#pragma unroll
            for (int mt = 0; mt < 2; mt++)
#pragma unroll
                for (int nt2 = 0; nt2 < 4; nt2++) {
                    MMA_TF32(acc[mt][nt2], ah[mt][0], ah[mt][1], ah[mt][2], ah[mt][3],
                             bh[nt2][0], bh[nt2][1]);
                    MMA_TF32(acc[mt][nt2], al[mt][0], al[mt][1], al[mt][2], al[mt][3],
                             bh[nt2][0], bh[nt2][1]);
                    MMA_TF32(acc[mt][nt2], ah[mt][0], ah[mt][1], ah[mt][2], ah[mt][3],
                             bl[nt2][0], bl[nt2][1]);
                }
        }
    }

    // epilogue
#pragma unroll
    for (int mt = 0; mt < 2; mt++) {
#pragma unroll
        for (int nt2 = 0; nt2 < 4; nt2++) {
            int col = bn0 + wn + nt2 * 8 + 2 * qq;
            int r0  = bm0 + wm + mt * 16 + g;
            float blo = bias[col], bhi = bias[col + 1];
            float2 o0, o1;
            o0.x = (acc[mt][nt2][0] + blo) * scale;
            o0.y = (acc[mt][nt2][1] + bhi) * scale;
            o1.x = (acc[mt][nt2][2] + blo) * scale;
            o1.y = (acc[mt][nt2][3] + bhi) * scale;
            if (EPI == 1) {
                o0.x = gelu_f(o0.x); o0.y = gelu_f(o0.y);
                o1.x = gelu_f(o1.x); o1.y = gelu_f(o1.y);
            }
            *(float2*)&C[(size_t)r0       * Nc + col] = o0;
            *(float2*)&C[(size_t)(r0 + 8) * Nc + col] = o1;
        }
    }
}

// -------------------- attention scores (reads packed qkv) --------------------
__global__ void __launch_bounds__(256)
scores_k(const float* __restrict__ qkv, const float* __restrict__ bias,
         float* __restrict__ sc) {
    int bh = blockIdx.x;
    int b = bh / H_, h = bh % H_;
    int n0 = blockIdx.y * 32, m0 = blockIdx.z * 32;
    __shared__ float Qs[32][25], Ks[32][25];
    int tid = threadIdx.x;
    for (int i = tid; i < 32*24; i += 256) {
        int r = i / 24, d = i % 24;
        Qs[r][d] = qkv[((size_t)(n0+r)*B_ + b)*QKV + h*D_ + d];
        Ks[r][d] = qkv[((size_t)(m0+r)*B_ + b)*QKV + E_ + h*D_ + d];
    }
    __syncthreads();
    int tx = tid & 31, ty = tid >> 5;
    int base = (bh*Nn + n0) * Nn;
    const float scaling = 0.20412414523193154f;  // 24^-0.5
#pragma unroll
    for (int i = 0; i < 4; i++) {
        int nl = (ty << 2) + i;
        float acc = 0.f;
#pragma unroll
        for (int d = 0; d < 24; d++) acc += Qs[nl][d] * Ks[tx][d];
        int o = base + nl*Nn + m0 + tx;
        sc[o] = acc * scaling + bias[o];
    }
}

// -------------------- softmax over last dim (Nn=384), in place ----------------
__global__ void __launch_bounds__(128)
softmax_k(float* __restrict__ sc, const int* __restrict__ nt) {
    int row = blockIdx.x;
    int b = row / (H_*Nn);
    float* p = sc + (size_t)row * Nn;
    int tid = threadIdx.x;
    float vv[3]; float mx = -3.4e38f;
#pragma unroll
    for (int i = 0; i < 3; i++) {
        int m = tid + (i << 7);
        float val = p[m];
        if (nt[b*Nn + m] == 0) val = __int_as_float(0xff800000);
        vv[i] = val; mx = fmaxf(mx, val);
    }
    __shared__ float r1[4], r2[4];
    for (int o = 16; o; o >>= 1) mx = fmaxf(mx, __shfl_xor_sync(0xffffffffu, mx, o));
    if ((tid & 31) == 0) r1[tid >> 5] = mx;
    __syncthreads();
    mx = fmaxf(fmaxf(r1[0], r1[1]), fmaxf(r1[2], r1[3]));
    float sum = 0.f;
#pragma unroll
    for (int i = 0; i < 3; i++) { vv[i] = __expf(vv[i] - mx); sum += vv[i]; }
    for (int o = 16; o; o >>= 1) sum += __shfl_xor_sync(0xffffffffu, sum, o);
    if ((tid & 31) == 0) r2[tid >> 5] = sum;
    __syncthreads();
    sum = r2[0] + r2[1] + r2[2] + r2[3];
    float inv = 1.f / sum;
#pragma unroll
    for (int i = 0; i < 3; i++) p[tid + (i << 7)] = vv[i] * inv;
}

// -------------------- PV (reads packed qkv V slice) --------------------------
__global__ void __launch_bounds__(256)
pv_k(const float* __restrict__ sc, const float* __restrict__ qkv, float* __restrict__ out) {
    int bh = blockIdx.x; int b = bh / H_, h = bh % H_;
    int n0 = blockIdx.y * 32;
    __shared__ float Ps[32][64];
    __shared__ float Vs[64][25];
    int tid = threadIdx.x;
    float acc[3] = {0.f, 0.f, 0.f};
    for (int mt = 0; mt < Nn; mt += 64) {
        for (int i = tid; i < 32*64; i += 256) {
            int r = i >> 6, c = i & 63;
            Ps[r][c] = sc[(bh*Nn + n0 + r)*Nn + mt + c];
        }
        for (int i = tid; i < 64*24; i += 256) {
            int r = i / 24, d = i % 24;
            Vs[r][d] = qkv[((size_t)(mt+r)*B_ + b)*QKV + 2*E_ + h*D_ + d];
        }
        __syncthreads();
#pragma unroll
        for (int j = 0; j < 3; j++) {
            int o = tid + (j << 8);
            int nl = o / 24, d = o % 24;
            float a = 0.f;
#pragma unroll
            for (int m = 0; m < 64; m++) a += Ps[nl][m] * Vs[m][d];
            acc[j] += a;
        }
        __syncthreads();
    }
#pragma unroll
    for (int j = 0; j < 3; j++) {
        int o = tid + (j << 8);
        int nl = o / 24, d = o % 24;
        out[((size_t)(n0+nl)*B_ + b)*E_ + h*D_ + d] = acc[j];
    }
}

// -------------------- residual add + LayerNorm --------------------
__global__ void __launch_bounds__(256)
ln_k(const float* __restrict__ x, const float* __restrict__ a,
     const float* __restrict__ s, const float* __restrict__ bb, float* __restrict__ out) {
    __shared__ float r1[8], r2[8];
    int t = blockIdx.x, tid = threadIdx.x;
    const float* xp = x + (size_t)t * E_;
    const float* ap = a + (size_t)t * E_;
    float v[3]; float sum = 0.f;
#pragma unroll
    for (int i = 0; i < 3; i++) { int e = tid + (i << 8); v[i] = xp[e] + ap[e]; sum += v[i]; }
    for (int o = 16; o; o >>= 1) sum += __shfl_xor_sync(0xffffffffu, sum, o);
    if ((tid & 31) == 0) r1[tid >> 5] = sum;
    __syncthreads();
    sum = 0.f;
#pragma unroll
    for (int w = 0; w < 8; w++) sum += r1[w];
    float mu = sum * (1.f / 768.f);
    float var = 0.f;
#pragma unroll
    for (int i = 0; i < 3; i++) { float d = v[i] - mu; var += d * d; }
    for (int o = 16; o; o >>= 1) var += __shfl_xor_sync(0xffffffffu, var, o);
    if ((tid & 31) == 0) r2[tid >> 5] = var;
    __syncthreads();
    var = 0.f;
#pragma unroll
    for (int w = 0; w < 8; w++) var += r2[w];
    float rstd = rsqrtf(var * (1.f / 768.f) + 1e-5f);
    float* op = out + (size_t)t * E_;
#pragma unroll
    for (int i = 0; i < 3; i++) {
        int e = tid + (i << 8);
        op[e] = (v[i] - mu) * rstd * s[e] + bb[e];
    }
}

// -------------------- orchestration --------------------
extern "C" void kernel_launch(void* const* d_in, const int* in_sizes, int n_in,
                              void* d_out, int out_size) {
    const int*   nt    = (const int*)  d_in[0];
    const float* nif   = (const float*)d_in[1];
    const int*   ind   = (const int*)  d_in[2];
    const int*   outd  = (const int*)  d_in[3];
    const float* ab    = (const float*)d_in[4];
    const int*   sp    = (const int*)  d_in[5];
    const float* nemb  = (const float*)d_in[6];
    const float* iemb  = (const float*)d_in[7];
    const float* oemb  = (const float*)d_in[8];
    const float* se    = (const float*)d_in[9];
    const float* ser   = (const float*)d_in[10];
    const float* Wq    = (const float*)d_in[11];
    const float* bq    = (const float*)d_in[12];
    const float* Wk    = (const float*)d_in[13];
    const float* bk    = (const float*)d_in[14];
    const float* Wv    = (const float*)d_in[15];
    const float* bv    = (const float*)d_in[16];
    const float* Wo    = (const float*)d_in[17];
    const float* bo    = (const float*)d_in[18];
    const float* W1    = (const float*)d_in[19];
    const float* b1    = (const float*)d_in[20];
    const float* W2    = (const float*)d_in[21];
    const float* b2    = (const float*)d_in[22];
    const float* ln1s  = (const float*)d_in[23];
    const float* ln1b  = (const float*)d_in[24];
    const float* ln2s  = (const float*)d_in[25];
    const float* ln2b  = (const float*)d_in[26];
    float* out = (float*)d_out;

    float *x, *q, *k, *h, *bias, *sc, *wqkv, *bqkv;
    cudaGetSymbolAddress((void**)&x,    g_x);
    cudaGetSymbolAddress((void**)&q,    g_q);
    cudaGetSymbolAddress((void**)&k,    g_k);
    cudaGetSymbolAddress((void**)&h,    g_h);
    cudaGetSymbolAddress((void**)&bias, g_bias);
    cudaGetSymbolAddress((void**)&sc,   g_sc);
    cudaGetSymbolAddress((void**)&wqkv, g_wqkv);
    cudaGetSymbolAddress((void**)&bqkv, g_bqkv);

    // pack QKV weights/biases (per launch; deterministic)
    long wtot = (long)L_*E_*QKV;
    packw_k<<<(unsigned)((wtot + 255)/256), 256>>>(Wq, Wk, Wv, wqkv);
    packb_k<<<(L_*QKV + 255)/256, 256>>>(bq, bk, bv, bqkv);

    embed_k<<<(T_*E_ + 255)/256, 256>>>(nt, nif, ind, outd, nemb, iemb, oemb, x);
    long btot = (long)B_*H_*Nn*Nn;
    bias_k<<<(unsigned)((btot + 255)/256), 256>>>(sp, ab, se, ser, bias);

    dim3 gQKV(QKV/BN, T_/BM);     // (36, 12)
    dim3 gE(E_/BN, T_/BM);        // (12, 12)
    dim3 gF1(F_/BN, T_/BM);       // (48, 12)
    dim3 gs(B_*H_, Nn/32, Nn/32); // (128, 12, 12)
    dim3 gpv(B_*H_, Nn/32);       // (128, 12)

    for (int l = 0; l < L_; l++) {
        const float* wo = Wo + (size_t)l*E_*E_;
        const float* w1 = W1 + (size_t)l*E_*F_;
        const float* w2 = W2 + (size_t)l*F_*E_;

        tgemm_k<0><<<gQKV, 256>>>(x, wqkv + (size_t)l*E_*QKV, bqkv + l*QKV, h,
                                  T_, E_, QKV, 1.f);

        scores_k<<<gs, 256>>>(h, bias, sc);
        softmax_k<<<B_*H_*Nn, 128>>>(sc, nt);
        pv_k<<<gpv, 256>>>(sc, h, q);                       // q := attention context

        tgemm_k<0><<<gE, 256>>>(q, wo, bo + l*E_, k, T_, E_, E_, 1.f);  // k := O-proj
        ln_k<<<T_, 256>>>(x, k, ln1s + l*E_, ln1b + l*E_, x);

        tgemm_k<1><<<gF1, 256>>>(x, w1, b1 + l*F_, h, T_, E_, F_, 1.f);  // gelu fused
        tgemm_k<0><<<gE, 256>>>(h, w2, b2 + l*E_, q, T_, F_, E_, 1.f);   // q := FFN out

        float* dst = (l == L_-1) ? out : x;
        ln_k<<<T_, 256>>>(x, q, ln2s + l*E_, ln2b + l*E_, dst);
    }
}

// round 6
// speedup vs baseline: 1.2208x; 1.2208x over previous
#include <cuda_runtime.h>
#include <cuda_bf16.h>
#include <math.h>

#define B_  4
#define Nn  384
#define E_  768
#define H_  32
#define F_  3072
#define L_  12
#define S_  512
#define D_  24
#define T_  (B_*Nn)          // 1536 tokens
#define QKV 2304             // 3*E

// -------------------- scratch (static device allocations) --------------------
__device__ float g_x   [T_*E_];
__device__ float g_tmp [T_*E_];
__device__ float g_qkv [T_*QKV];
__device__ float g_bias[B_*H_*Nn*Nn];
__device__ float g_sc  [B_*H_*Nn*Nn];
__device__ float g_bqkv[L_*QKV];
// bf16 hi/lo activation buffers
__device__ __nv_bfloat16 g_xh[T_*E_],  g_xl[T_*E_];
__device__ __nv_bfloat16 g_ch[T_*E_],  g_cl[T_*E_];
__device__ __nv_bfloat16 g_hh[T_*F_],  g_hl[T_*F_];
// bf16 hi/lo transposed weights, [l][n][k]
__device__ __nv_bfloat16 g_wqkvh[(size_t)L_*QKV*E_], g_wqkvl[(size_t)L_*QKV*E_];
__device__ __nv_bfloat16 g_woh  [(size_t)L_*E_*E_],  g_wol  [(size_t)L_*E_*E_];
__device__ __nv_bfloat16 g_w1h  [(size_t)L_*F_*E_],  g_w1l  [(size_t)L_*F_*E_];
__device__ __nv_bfloat16 g_w2h  [(size_t)L_*E_*F_],  g_w2l  [(size_t)L_*E_*F_];

// ==================== helpers ====================
__device__ __forceinline__ float gelu_f(float x) {
    return 0.5f * x * (1.0f + tanhf(0.7978845608028654f * (x + 0.044715f * x * x * x)));
}
__device__ __forceinline__ unsigned smem_u32(const void* p) {
    return (unsigned)__cvta_generic_to_shared(p);
}
#define CP_ASYNC16(dst, src) \
    asm volatile("cp.async.cg.shared.global [%0], [%1], 16;\n" :: "r"(dst), "l"(src) : "memory")
#define CP_COMMIT() asm volatile("cp.async.commit_group;\n" ::: "memory")
#define CP_WAIT1()  asm volatile("cp.async.wait_group 1;\n" ::: "memory")

#define MMA_BF16(acc, a, b) \
    asm volatile("mma.sync.aligned.m16n8k16.row.col.f32.bf16.bf16.f32 " \
        "{%0,%1,%2,%3}, {%4,%5,%6,%7}, {%8,%9}, {%0,%1,%2,%3};" \
        : "+f"((acc)[0]), "+f"((acc)[1]), "+f"((acc)[2]), "+f"((acc)[3]) \
        : "r"((a)[0]), "r"((a)[1]), "r"((a)[2]), "r"((a)[3]), "r"((b)[0]), "r"((b)[1]))

__device__ __forceinline__ void split_bf(float v, __nv_bfloat16& h, __nv_bfloat16& l) {
    h = __float2bfloat16_rn(v);
    l = __float2bfloat16_rn(v - __bfloat162float(h));
}

// ==================== weight transpose + bf16 split ====================
// src: fp32 [K][N] row-major per layer. dst: bf16 [N][K] hi/lo.
__global__ void __launch_bounds__(256)
tr_k(const float* __restrict__ src, __nv_bfloat16* __restrict__ dh,
     __nv_bfloat16* __restrict__ dl, int K, int N,
     size_t sLs, size_t dLs, int ro) {
    __shared__ float tile[32][33];
    int l = blockIdx.z;
    int n0 = blockIdx.x * 32, k0 = blockIdx.y * 32;
    int tx = threadIdx.x & 31, ty = threadIdx.x >> 5;
    const float* s = src + (size_t)l * sLs;
#pragma unroll
    for (int r = 0; r < 4; r++)
        tile[ty + r*8][tx] = s[(size_t)(k0 + ty + r*8) * N + n0 + tx];
    __syncthreads();
#pragma unroll
    for (int r = 0; r < 4; r++) {
        int n = n0 + ty + r*8, k = k0 + tx;
        float v = tile[tx][ty + r*8];
        __nv_bfloat16 h, lo; split_bf(v, h, lo);
        size_t di = (size_t)l * dLs + (size_t)(ro + n) * K + k;
        dh[di] = h; dl[di] = lo;
    }
}
__global__ void packb_k(const float* __restrict__ bq, const float* __restrict__ bk,
                        const float* __restrict__ bv, float* __restrict__ bo) {
    int idx = blockIdx.x * blockDim.x + threadIdx.x;
    if (idx >= L_*QKV) return;
    int n = idx % QKV, l = idx / QKV;
    float v;
    if      (n < E_)   v = bq[l*E_ + n];
    else if (n < 2*E_) v = bk[l*E_ + n - E_];
    else               v = bv[l*E_ + n - 2*E_];
    bo[idx] = v;
}

// ==================== embedding (fp32 + bf16 hi/lo) ====================
__global__ void embed_k(const int* __restrict__ nt, const float* __restrict__ nif,
                        const int* __restrict__ ind, const int* __restrict__ outd,
                        const float* __restrict__ nemb, const float* __restrict__ iemb,
                        const float* __restrict__ oemb, float* __restrict__ x,
                        __nv_bfloat16* __restrict__ xh, __nv_bfloat16* __restrict__ xl) {
    int idx = blockIdx.x * blockDim.x + threadIdx.x;
    if (idx >= T_*E_) return;
    int e = idx % E_, tok = idx / E_;
    int b = tok % B_, n = tok / B_;
    int bn = b*Nn + n;
    int t  = nt[bn];
    float v = nemb[t*E_+e] + iemb[ind[bn]*E_+e] + oemb[outd[bn]*E_+e] + nif[(size_t)bn*E_+e];
    x[idx] = v;
    __nv_bfloat16 h, lo; split_bf(v, h, lo);
    xh[idx] = h; xl[idx] = lo;
}

// ==================== spatial bias (tiled) ====================
__global__ void __launch_bounds__(256)
bias_k(const int* __restrict__ sp, const float* __restrict__ ab,
       const float* __restrict__ se, const float* __restrict__ ser,
       float* __restrict__ bias) {
    int b = blockIdx.x, n0 = blockIdx.y * 32, m0 = blockIdx.z * 32;
    __shared__ int s1t[32][33];
    __shared__ int s2t[32][33];
    __shared__ float abt[32][33];
    int tid = threadIdx.x;
    for (int i = tid; i < 1024; i += 256) {
        int r = i >> 5, cc = i & 31;
        s1t[r][cc] = sp[((size_t)(b*Nn) + n0 + r) * Nn + m0 + cc];
        s2t[r][cc] = sp[((size_t)(b*Nn) + m0 + r) * Nn + n0 + cc];
        abt[r][cc] = ab[((size_t)(b*Nn) + n0 + r) * Nn + m0 + cc];
    }
    __syncthreads();
    for (int h = 0; h < H_; h++) {
        for (int i = tid; i < 1024; i += 256) {
            int r = i >> 5, cc = i & 31;
            float v = se[s1t[r][cc] * H_ + h] + ser[s2t[cc][r] * H_ + h] + abt[r][cc];
            bias[(((size_t)(b*H_ + h) * Nn) + n0 + r) * Nn + m0 + cc] = v;
        }
    }
}

// ==================== bf16x3 tensor-core GEMM (mma.sync m16n8k16) ============
// C[M,Nc] = epi((Ah+Al)[M,K] @ (Wh+Wl)[K,Nc]^T-stored + bias) * scale)
// A: bf16 hi/lo [M][K] row-major. W: bf16 hi/lo [Nc][K] row-major (pre-transposed).
// Block 128x64, BK=32, 8 warps (4m x 2n), warp tile 32x32, 3-stage cp.async.
// smem/stage: Ah 10240 | Al 10240 | Bh 5120 | Bl 5120  (rows stride 80B = 20 u32)
#define RS   20
#define STG  30720
#define GSMT (3*STG)

#define GISSUE(t, s) do { \
    unsigned so_ = sb + (unsigned)(s)*STG; \
    unsigned da_ = so_ + arow*80u + ac0*16u; \
    const char* gah_ = Agh + (size_t)(t)*64 + ac0*16; \
    const char* gal_ = Agl + (size_t)(t)*64 + ac0*16; \
    CP_ASYNC16(da_, gah_); CP_ASYNC16(da_+16u, gah_+16); \
    CP_ASYNC16(da_+10240u, gal_); CP_ASYNC16(da_+10256u, gal_+16); \
    unsigned db_ = so_ + 20480u + brow*80u + bc*16u; \
    CP_ASYNC16(db_, Bgh + (size_t)(t)*64 + bc*16); \
    CP_ASYNC16(db_+5120u, Bgl + (size_t)(t)*64 + bc*16); \
} while (0)

template<int EPI>  // 0 = bias -> fp32 C;  1 = bias+gelu -> bf16 hi/lo Ch/Cl
__global__ void __launch_bounds__(256, 2)
mma_gemm(const __nv_bfloat16* __restrict__ Ah, const __nv_bfloat16* __restrict__ Al,
         const __nv_bfloat16* __restrict__ Wh, const __nv_bfloat16* __restrict__ Wl,
         const float* __restrict__ bias, float* __restrict__ C,
         __nv_bfloat16* __restrict__ Ch, __nv_bfloat16* __restrict__ Cl,
         int M, int K, int Nc, float scale) {
    extern __shared__ char sm[];
    unsigned sb = smem_u32(sm);
    int tid = threadIdx.x, wid = tid >> 5, lane = tid & 31;
    int g = lane >> 2, q = lane & 3;
    int wm = (wid & 3) * 32, wn = (wid >> 2) * 32;
    int bm0 = blockIdx.y * 128, bn0 = blockIdx.x * 64;

    // producer mapping
    unsigned arow = tid >> 1;        // 0..127
    unsigned ac0  = (tid & 1) * 2;   // chunk 0 or 2
    unsigned brow = tid >> 2;        // 0..63
    unsigned bc   = tid & 3;         // chunk 0..3
    const char* Agh = (const char*)(Ah + (size_t)(bm0 + arow) * K);
    const char* Agl = (const char*)(Al + (size_t)(bm0 + arow) * K);
    const char* Bgh = (const char*)(Wh + (size_t)(bn0 + brow) * K);
    const char* Bgl = (const char*)(Wl + (size_t)(bn0 + brow) * K);

    float acc[2][4][4];
#pragma unroll
    for (int i = 0; i < 2; i++)
#pragma unroll
        for (int j = 0; j < 4; j++)
#pragma unroll
            for (int c = 0; c < 4; c++) acc[i][j][c] = 0.f;

    int ntiles = K >> 5;
    GISSUE(0, 0); CP_COMMIT();
    GISSUE(1, 1); CP_COMMIT();

    for (int t = 0; t < ntiles; t++) {
        CP_WAIT1();
        __syncthreads();
        int tn = t + 2;
        if (tn < ntiles) { int s2 = tn % 3; GISSUE(tn, s2); }
        CP_COMMIT();

        const unsigned* Ahs = (const unsigned*)(sm + (t % 3) * STG);
        const unsigned* Als = Ahs + 2560;
        const unsigned* Bhs = Ahs + 5120;
        const unsigned* Bls = Ahs + 6400;
#pragma unroll
        for (int kk = 0; kk < 2; kk++) {
            int kb = kk * 8;
            unsigned ah[2][4], al[2][4], bh[4][2], bl[4][2];
#pragma unroll
            for (int mt = 0; mt < 2; mt++) {
                int r0 = (wm + mt*16 + g) * RS;
                int r1 = r0 + 8 * RS;
                ah[mt][0] = Ahs[r0 + kb + q];     ah[mt][1] = Ahs[r1 + kb + q];
                ah[mt][2] = Ahs[r0 + kb + q + 4]; ah[mt][3] = Ahs[r1 + kb + q + 4];
                al[mt][0] = Als[r0 + kb + q];     al[mt][1] = Als[r1 + kb + q];
                al[mt][2] = Als[r0 + kb + q + 4]; al[mt][3] = Als[r1 + kb + q + 4];
            }
#pragma unroll
            for (int nt = 0; nt < 4; nt++) {
                int rn = (wn + nt*8 + g) * RS;
                bh[nt][0] = Bhs[rn + kb + q]; bh[nt][1] = Bhs[rn + kb + q + 4];
                bl[nt][0] = Bls[rn + kb + q]; bl[nt][1] = Bls[rn + kb + q + 4];
            }
#pragma unroll
            for (int mt = 0; mt < 2; mt++)
#pragma unroll
                for (int nt = 0; nt < 4; nt++) {
                    MMA_BF16(acc[mt][nt], ah[mt], bh[nt]);
                    MMA_BF16(acc[mt][nt], al[mt], bh[nt]);
                    MMA_BF16(acc[mt][nt], ah[mt], bl[nt]);
                }
        }
    }

    // epilogue: c0,c1 = (row g, cols 2q,2q+1); c2,c3 = (row g+8)
#pragma unroll
    for (int mt = 0; mt < 2; mt++) {
#pragma unroll
        for (int nt = 0; nt < 4; nt++) {
            int col = bn0 + wn + nt*8 + 2*q;
            int r0  = bm0 + wm + mt*16 + g;
            float blo = bias[col], bhi = bias[col + 1];
            float v00 = (acc[mt][nt][0] + blo) * scale;
            float v01 = (acc[mt][nt][1] + bhi) * scale;
            float v10 = (acc[mt][nt][2] + blo) * scale;
            float v11 = (acc[mt][nt][3] + bhi) * scale;
            if (EPI == 0) {
                *(float2*)&C[(size_t)r0       * Nc + col] = make_float2(v00, v01);
                *(float2*)&C[(size_t)(r0 + 8) * Nc + col] = make_float2(v10, v11);
            } else {
                v00 = gelu_f(v00); v01 = gelu_f(v01);
                v10 = gelu_f(v10); v11 = gelu_f(v11);
                __nv_bfloat16 h0, l0, h1, l1;
                split_bf(v00, h0, l0); split_bf(v01, h1, l1);
                { __nv_bfloat162 hp; hp.x = h0; hp.y = h1;
                  *(__nv_bfloat162*)&Ch[(size_t)r0 * Nc + col] = hp;
                  __nv_bfloat162 lp; lp.x = l0; lp.y = l1;
                  *(__nv_bfloat162*)&Cl[(size_t)r0 * Nc + col] = lp; }
                split_bf(v10, h0, l0); split_bf(v11, h1, l1);
                { __nv_bfloat162 hp; hp.x = h0; hp.y = h1;
                  *(__nv_bfloat162*)&Ch[(size_t)(r0 + 8) * Nc + col] = hp;
                  __nv_bfloat162 lp; lp.x = l0; lp.y = l1;
                  *(__nv_bfloat162*)&Cl[(size_t)(r0 + 8) * Nc + col] = lp; }
            }
        }
    }
}

// ==================== attention scores ====================
__global__ void __launch_bounds__(256)
scores_k(const float* __restrict__ qkv, const float* __restrict__ bias,
         float* __restrict__ sc) {
    int bh = blockIdx.x;
    int b = bh / H_, h = bh % H_;
    int n0 = blockIdx.y * 32, m0 = blockIdx.z * 32;
    __shared__ float Qs[32][25], Ks[32][25];
    int tid = threadIdx.x;
    for (int i = tid; i < 32*24; i += 256) {
        int r = i / 24, d = i % 24;
        Qs[r][d] = qkv[((size_t)(n0+r)*B_ + b)*QKV + h*D_ + d];
        Ks[r][d] = qkv[((size_t)(m0+r)*B_ + b)*QKV + E_ + h*D_ + d];
    }
    __syncthreads();
    int tx = tid & 31, ty = tid >> 5;
    int base = (bh*Nn + n0) * Nn;
    const float scaling = 0.20412414523193154f;  // 24^-0.5
#pragma unroll
    for (int i = 0; i < 4; i++) {
        int nl = (ty << 2) + i;
        float acc = 0.f;
#pragma unroll
        for (int d = 0; d < 24; d++) acc += Qs[nl][d] * Ks[tx][d];
        int o = base + nl*Nn + m0 + tx;
        sc[o] = acc * scaling + bias[o];
    }
}

// ==================== softmax (in place) ====================
__global__ void __launch_bounds__(128)
softmax_k(float* __restrict__ sc, const int* __restrict__ nt) {
    int row = blockIdx.x;
    int b = row / (H_*Nn);
    float* p = sc + (size_t)row * Nn;
    int tid = threadIdx.x;
    float vv[3]; float mx = -3.4e38f;
#pragma unroll
    for (int i = 0; i < 3; i++) {
        int m = tid + (i << 7);
        float val = p[m];
        if (nt[b*Nn + m] == 0) val = __int_as_float(0xff800000);
        vv[i] = val; mx = fmaxf(mx, val);
    }
    __shared__ float r1[4], r2[4];
    for (int o = 16; o; o >>= 1) mx = fmaxf(mx, __shfl_xor_sync(0xffffffffu, mx, o));
    if ((tid & 31) == 0) r1[tid >> 5] = mx;
    __syncthreads();
    mx = fmaxf(fmaxf(r1[0], r1[1]), fmaxf(r1[2], r1[3]));
    float sum = 0.f;
#pragma unroll
    for (int i = 0; i < 3; i++) { vv[i] = __expf(vv[i] - mx); sum += vv[i]; }
    for (int o = 16; o; o >>= 1) sum += __shfl_xor_sync(0xffffffffu, sum, o);
    if ((tid & 31) == 0) r2[tid >> 5] = sum;
    __syncthreads();
    sum = r2[0] + r2[1] + r2[2] + r2[3];
    float inv = 1.f / sum;
#pragma unroll
    for (int i = 0; i < 3; i++) p[tid + (i << 7)] = vv[i] * inv;
}

// ==================== PV (writes bf16 hi/lo ctx) ====================
__global__ void __launch_bounds__(256)
pv_k(const float* __restrict__ sc, const float* __restrict__ qkv,
     __nv_bfloat16* __restrict__ oh, __nv_bfloat16* __restrict__ ol) {
    int bh = blockIdx.x; int b = bh / H_, h = bh % H_;
    int n0 = blockIdx.y * 32;
    __shared__ float Ps[32][64];
    __shared__ float Vs[64][25];
    int tid = threadIdx.x;
    float acc[3] = {0.f, 0.f, 0.f};
    for (int mt = 0; mt < Nn; mt += 64) {
        for (int i = tid; i < 32*64; i += 256) {
            int r = i >> 6, c = i & 63;
            Ps[r][c] = sc[(bh*Nn + n0 + r)*Nn + mt + c];
        }
        for (int i = tid; i < 64*24; i += 256) {
            int r = i / 24, d = i % 24;
            Vs[r][d] = qkv[((size_t)(mt+r)*B_ + b)*QKV + 2*E_ + h*D_ + d];
        }
        __syncthreads();
#pragma unroll
        for (int j = 0; j < 3; j++) {
            int o = tid + (j << 8);
            int nl = o / 24, d = o % 24;
            float a = 0.f;
#pragma unroll
            for (int m = 0; m < 64; m++) a += Ps[nl][m] * Vs[m][d];
            acc[j] += a;
        }
        __syncthreads();
    }
#pragma unroll
    for (int j = 0; j < 3; j++) {
        int o = tid + (j << 8);
        int nl = o / 24, d = o % 24;
        size_t idx = ((size_t)(n0+nl)*B_ + b)*E_ + h*D_ + d;
        __nv_bfloat16 hh, ll; split_bf(acc[j], hh, ll);
        oh[idx] = hh; ol[idx] = ll;
    }
}

// ==================== residual add + LayerNorm (+ bf16 hi/lo out) ============
__global__ void __launch_bounds__(256)
ln_k(const float* __restrict__ x, const float* __restrict__ a,
     const float* __restrict__ s, const float* __restrict__ bb,
     float* __restrict__ out,
     __nv_bfloat16* __restrict__ oh, __nv_bfloat16* __restrict__ ol) {
    __shared__ float r1[8], r2[8];
    int t = blockIdx.x, tid = threadIdx.x;
    const float* xp = x + (size_t)t * E_;
    const float* ap = a + (size_t)t * E_;
    float v[3]; float sum = 0.f;
#pragma unroll
    for (int i = 0; i < 3; i++) { int e = tid + (i << 8); v[i] = xp[e] + ap[e]; sum += v[i]; }
    for (int o = 16; o; o >>= 1) sum += __shfl_xor_sync(0xffffffffu, sum, o);
    if ((tid & 31) == 0) r1[tid >> 5] = sum;
    __syncthreads();
    sum = 0.f;
#pragma unroll
    for (int w = 0; w < 8; w++) sum += r1[w];
    float mu = sum * (1.f / 768.f);
    float var = 0.f;
#pragma unroll
    for (int i = 0; i < 3; i++) { float d = v[i] - mu; var += d * d; }
    for (int o = 16; o; o >>= 1) var += __shfl_xor_sync(0xffffffffu, var, o);
    if ((tid & 31) == 0) r2[tid >> 5] = var;
    __syncthreads();
    var = 0.f;
#pragma unroll
    for (int w = 0; w < 8; w++) var += r2[w];
    float rstd = rsqrtf(var * (1.f / 768.f) + 1e-5f);
#pragma unroll
    for (int i = 0; i < 3; i++) {
        int e = tid + (i << 8);
        float o = (v[i] - mu) * rstd * s[e] + bb[e];
        out[(size_t)t * E_ + e] = o;
        __nv_bfloat16 hh, ll; split_bf(o, hh, ll);
        oh[(size_t)t * E_ + e] = hh; ol[(size_t)t * E_ + e] = ll;
    }
}

// ==================== orchestration ====================
extern "C" void kernel_launch(void* const* d_in, const int* in_sizes, int n_in,
                              void* d_out, int out_size) {
    const int*   nt    = (const int*)  d_in[0];
    const float* nif   = (const float*)d_in[1];
    const int*   ind   = (const int*)  d_in[2];
    const int*   outd  = (const int*)  d_in[3];
    const float* ab    = (const float*)d_in[4];
    const int*   sp    = (const int*)  d_in[5];
    const float* nemb  = (const float*)d_in[6];
    const float* iemb  = (const float*)d_in[7];
    const float* oemb  = (const float*)d_in[8];
    const float* se    = (const float*)d_in[9];
    const float* ser   = (const float*)d_in[10];
    const float* Wq    = (const float*)d_in[11];
    const float* bq    = (const float*)d_in[12];
    const float* Wk    = (const float*)d_in[13];
    const float* bk    = (const float*)d_in[14];
    const float* Wv    = (const float*)d_in[15];
    const float* bv    = (const float*)d_in[16];
    const float* Wo    = (const float*)d_in[17];
    const float* bo    = (const float*)d_in[18];
    const float* W1    = (const float*)d_in[19];
    const float* b1    = (const float*)d_in[20];
    const float* W2    = (const float*)d_in[21];
    const float* b2    = (const float*)d_in[22];
    const float* ln1s  = (const float*)d_in[23];
    const float* ln1b  = (const float*)d_in[24];
    const float* ln2s  = (const float*)d_in[25];
    const float* ln2b  = (const float*)d_in[26];
    float* out = (float*)d_out;

    float *x, *tmp, *qkv, *bias, *sc, *bqkv;
    __nv_bfloat16 *xh, *xl, *ch, *cl, *hh, *hl;
    __nv_bfloat16 *wqkvh, *wqkvl, *woh, *wol, *w1h, *w1l, *w2h, *w2l;
    cudaGetSymbolAddress((void**)&x,    g_x);
    cudaGetSymbolAddress((void**)&tmp,  g_tmp);
    cudaGetSymbolAddress((void**)&qkv,  g_qkv);
    cudaGetSymbolAddress((void**)&bias, g_bias);
    cudaGetSymbolAddress((void**)&sc,   g_sc);
    cudaGetSymbolAddress((void**)&bqkv, g_bqkv);
    cudaGetSymbolAddress((void**)&xh,   g_xh);
    cudaGetSymbolAddress((void**)&xl,   g_xl);
    cudaGetSymbolAddress((void**)&ch,   g_ch);
    cudaGetSymbolAddress((void**)&cl,   g_cl);
    cudaGetSymbolAddress((void**)&hh,   g_hh);
    cudaGetSymbolAddress((void**)&hl,   g_hl);
    cudaGetSymbolAddress((void**)&wqkvh, g_wqkvh);
    cudaGetSymbolAddress((void**)&wqkvl, g_wqkvl);
    cudaGetSymbolAddress((void**)&woh,   g_woh);
    cudaGetSymbolAddress((void**)&wol,   g_wol);
    cudaGetSymbolAddress((void**)&w1h,   g_w1h);
    cudaGetSymbolAddress((void**)&w1l,   g_w1l);
    cudaGetSymbolAddress((void**)&w2h,   g_w2h);
    cudaGetSymbolAddress((void**)&w2l,   g_w2l);

    cudaFuncSetAttribute(mma_gemm<0>, cudaFuncAttributeMaxDynamicSharedMemorySize, GSMT);
    cudaFuncSetAttribute(mma_gemm<1>, cudaFuncAttributeMaxDynamicSharedMemorySize, GSMT);

    // ---- prepass: transpose + split weights, pack bias, embed, bias ----
    tr_k<<<dim3(E_/32, E_/32, L_), 256>>>(Wq, wqkvh, wqkvl, E_, E_,
        (size_t)E_*E_, (size_t)QKV*E_, 0);
    tr_k<<<dim3(E_/32, E_/32, L_), 256>>>(Wk, wqkvh, wqkvl, E_, E_,
        (size_t)E_*E_, (size_t)QKV*E_, E_);
    tr_k<<<dim3(E_/32, E_/32, L_), 256>>>(Wv, wqkvh, wqkvl, E_, E_,
        (size_t)E_*E_, (size_t)QKV*E_, 2*E_);
    tr_k<<<dim3(E_/32, E_/32, L_), 256>>>(Wo, woh, wol, E_, E_,
        (size_t)E_*E_, (size_t)E_*E_, 0);
    tr_k<<<dim3(F_/32, E_/32, L_), 256>>>(W1, w1h, w1l, E_, F_,
        (size_t)E_*F_, (size_t)F_*E_, 0);
    tr_k<<<dim3(E_/32, F_/32, L_), 256>>>(W2, w2h, w2l, F_, E_,
        (size_t)F_*E_, (size_t)E_*F_, 0);
    packb_k<<<(L_*QKV + 255)/256, 256>>>(bq, bk, bv, bqkv);

    embed_k<<<(T_*E_ + 255)/256, 256>>>(nt, nif, ind, outd, nemb, iemb, oemb, x, xh, xl);
    bias_k<<<dim3(B_, Nn/32, Nn/32), 256>>>(sp, ab, se, ser, bias);

    dim3 gQKV(QKV/64, T_/128);     // (36, 12)
    dim3 gE(E_/64, T_/128);        // (12, 12)
    dim3 gF1(F_/64, T_/128);       // (48, 12)
    dim3 gs(B_*H_, Nn/32, Nn/32);  // (128, 12, 12)
    dim3 gpv(B_*H_, Nn/32);        // (128, 12)

    for (int l = 0; l < L_; l++) {
        mma_gemm<0><<<gQKV, 256, GSMT>>>(xh, xl,
            wqkvh + (size_t)l*QKV*E_, wqkvl + (size_t)l*QKV*E_,
            bqkv + l*QKV, qkv, hh, hl, T_, E_, QKV, 1.f);

        scores_k<<<gs, 256>>>(qkv, bias, sc);
        softmax_k<<<B_*H_*Nn, 128>>>(sc, nt);
        pv_k<<<gpv, 256>>>(sc, qkv, ch, cl);

        mma_gemm<0><<<gE, 256, GSMT>>>(ch, cl,
            woh + (size_t)l*E_*E_, wol + (size_t)l*E_*E_,
            bo + l*E_, tmp, hh, hl, T_, E_, E_, 1.f);
        ln_k<<<T_, 256>>>(x, tmp, ln1s + l*E_, ln1b + l*E_, x, xh, xl);

        mma_gemm<1><<<gF1, 256, GSMT>>>(xh, xl,
            w1h + (size_t)l*F_*E_, w1l + (size_t)l*F_*E_,
            b1 + l*F_, tmp, hh, hl, T_, E_, F_, 1.f);
        mma_gemm<0><<<gE, 256, GSMT>>>(hh, hl,
            w2h + (size_t)l*E_*F_, w2l + (size_t)l*E_*F_,
            b2 + l*E_, tmp, hh, hl, T_, F_, E_, 1.f);

        float* dst = (l == L_-1) ? out : x;
        ln_k<<<T_, 256>>>(x, tmp, ln2s + l*E_, ln2b + l*E_, dst, xh, xl);
    }
}

// round 7
// speedup vs baseline: 1.2223x; 1.0012x over previous
#include <cuda_runtime.h>
#include <cuda_bf16.h>
#include <math.h>

#define B_  4
#define Nn  384
#define E_  768
#define H_  32
#define F_  3072
#define L_  12
#define S_  512
#define D_  24
#define T_  (B_*Nn)          // 1536 tokens
#define QKV 2304             // 3*E

// -------------------- scratch (static device allocations) --------------------
__device__ float g_x   [T_*E_];
__device__ float g_tmp [T_*E_];
__device__ float g_qkv [T_*QKV];
__device__ float g_bias[B_*H_*Nn*Nn];
__device__ float g_bqkv[L_*QKV];
// bf16 hi/lo activation buffers
__device__ __nv_bfloat16 g_xh[T_*E_],  g_xl[T_*E_];
__device__ __nv_bfloat16 g_ch[T_*E_],  g_cl[T_*E_];
__device__ __nv_bfloat16 g_hh[T_*F_],  g_hl[T_*F_];
// bf16 hi/lo transposed weights, [l][n][k]
__device__ __nv_bfloat16 g_wqkvh[(size_t)L_*QKV*E_], g_wqkvl[(size_t)L_*QKV*E_];
__device__ __nv_bfloat16 g_woh  [(size_t)L_*E_*E_],  g_wol  [(size_t)L_*E_*E_];
__device__ __nv_bfloat16 g_w1h  [(size_t)L_*F_*E_],  g_w1l  [(size_t)L_*F_*E_];
__device__ __nv_bfloat16 g_w2h  [(size_t)L_*E_*F_],  g_w2l  [(size_t)L_*E_*F_];

// ==================== helpers ====================
__device__ __forceinline__ float gelu_f(float x) {
    return 0.5f * x * (1.0f + tanhf(0.7978845608028654f * (x + 0.044715f * x * x * x)));
}
__device__ __forceinline__ unsigned smem_u32(const void* p) {
    return (unsigned)__cvta_generic_to_shared(p);
}
#define CP_ASYNC16(dst, src) \
    asm volatile("cp.async.cg.shared.global [%0], [%1], 16;\n" :: "r"(dst), "l"(src) : "memory")
#define CP_COMMIT() asm volatile("cp.async.commit_group;\n" ::: "memory")
#define CP_WAIT1()  asm volatile("cp.async.wait_group 1;\n" ::: "memory")

#define MMA_BF16(acc, a, b) \
    asm volatile("mma.sync.aligned.m16n8k16.row.col.f32.bf16.bf16.f32 " \
        "{%0,%1,%2,%3}, {%4,%5,%6,%7}, {%8,%9}, {%0,%1,%2,%3};" \
        : "+f"((acc)[0]), "+f"((acc)[1]), "+f"((acc)[2]), "+f"((acc)[3]) \
        : "r"((a)[0]), "r"((a)[1]), "r"((a)[2]), "r"((a)[3]), "r"((b)[0]), "r"((b)[1]))

__device__ __forceinline__ void split_bf(float v, __nv_bfloat16& h, __nv_bfloat16& l) {
    h = __float2bfloat16_rn(v);
    l = __float2bfloat16_rn(v - __bfloat162float(h));
}

// ==================== weight transpose + bf16 split ====================
__global__ void __launch_bounds__(256)
tr_k(const float* __restrict__ src, __nv_bfloat16* __restrict__ dh,
     __nv_bfloat16* __restrict__ dl, int K, int N,
     size_t sLs, size_t dLs, int ro) {
    __shared__ float tile[32][33];
    int l = blockIdx.z;
    int n0 = blockIdx.x * 32, k0 = blockIdx.y * 32;
    int tx = threadIdx.x & 31, ty = threadIdx.x >> 5;
    const float* s = src + (size_t)l * sLs;
#pragma unroll
    for (int r = 0; r < 4; r++)
        tile[ty + r*8][tx] = s[(size_t)(k0 + ty + r*8) * N + n0 + tx];
    __syncthreads();
#pragma unroll
    for (int r = 0; r < 4; r++) {
        int n = n0 + ty + r*8, k = k0 + tx;
        float v = tile[tx][ty + r*8];
        __nv_bfloat16 h, lo; split_bf(v, h, lo);
        size_t di = (size_t)l * dLs + (size_t)(ro + n) * K + k;
        dh[di] = h; dl[di] = lo;
    }
}
__global__ void packb_k(const float* __restrict__ bq, const float* __restrict__ bk,
                        const float* __restrict__ bv, float* __restrict__ bo) {
    int idx = blockIdx.x * blockDim.x + threadIdx.x;
    if (idx >= L_*QKV) return;
    int n = idx % QKV, l = idx / QKV;
    float v;
    if      (n < E_)   v = bq[l*E_ + n];
    else if (n < 2*E_) v = bk[l*E_ + n - E_];
    else               v = bv[l*E_ + n - 2*E_];
    bo[idx] = v;
}

// ==================== embedding (fp32 + bf16 hi/lo) ====================
__global__ void embed_k(const int* __restrict__ nt, const float* __restrict__ nif,
                        const int* __restrict__ ind, const int* __restrict__ outd,
                        const float* __restrict__ nemb, const float* __restrict__ iemb,
                        const float* __restrict__ oemb, float* __restrict__ x,
                        __nv_bfloat16* __restrict__ xh, __nv_bfloat16* __restrict__ xl) {
    int idx = blockIdx.x * blockDim.x + threadIdx.x;
    if (idx >= T_*E_) return;
    int e = idx % E_, tok = idx / E_;
    int b = tok % B_, n = tok / B_;
    int bn = b*Nn + n;
    int t  = nt[bn];
    float v = nemb[t*E_+e] + iemb[ind[bn]*E_+e] + oemb[outd[bn]*E_+e] + nif[(size_t)bn*E_+e];
    x[idx] = v;
    __nv_bfloat16 h, lo; split_bf(v, h, lo);
    xh[idx] = h; xl[idx] = lo;
}

// ==================== spatial bias (tiled) ====================
__global__ void __launch_bounds__(256)
bias_k(const int* __restrict__ sp, const float* __restrict__ ab,
       const float* __restrict__ se, const float* __restrict__ ser,
       float* __restrict__ bias) {
    int b = blockIdx.x, n0 = blockIdx.y * 32, m0 = blockIdx.z * 32;
    __shared__ int s1t[32][33];
    __shared__ int s2t[32][33];
    __shared__ float abt[32][33];
    int tid = threadIdx.x;
    for (int i = tid; i < 1024; i += 256) {
        int r = i >> 5, cc = i & 31;
        s1t[r][cc] = sp[((size_t)(b*Nn) + n0 + r) * Nn + m0 + cc];
        s2t[r][cc] = sp[((size_t)(b*Nn) + m0 + r) * Nn + n0 + cc];
        abt[r][cc] = ab[((size_t)(b*Nn) + n0 + r) * Nn + m0 + cc];
    }
    __syncthreads();
    for (int h = 0; h < H_; h++) {
        for (int i = tid; i < 1024; i += 256) {
            int r = i >> 5, cc = i & 31;
            float v = se[s1t[r][cc] * H_ + h] + ser[s2t[cc][r] * H_ + h] + abt[r][cc];
            bias[(((size_t)(b*H_ + h) * Nn) + n0 + r) * Nn + m0 + cc] = v;
        }
    }
}

// ==================== bf16x3 tensor-core GEMM (mma.sync m16n8k16) ============
#define RS   20
#define STG  30720
#define GSMT (3*STG)

#define GISSUE(t, s) do { \
    unsigned so_ = sb + (unsigned)(s)*STG; \
    unsigned da_ = so_ + arow*80u + ac0*16u; \
    const char* gah_ = Agh + (size_t)(t)*64 + ac0*16; \
    const char* gal_ = Agl + (size_t)(t)*64 + ac0*16; \
    CP_ASYNC16(da_, gah_); CP_ASYNC16(da_+16u, gah_+16); \
    CP_ASYNC16(da_+10240u, gal_); CP_ASYNC16(da_+10256u, gal_+16); \
    unsigned db_ = so_ + 20480u + brow*80u + bc*16u; \
    CP_ASYNC16(db_, Bgh + (size_t)(t)*64 + bc*16); \
    CP_ASYNC16(db_+5120u, Bgl + (size_t)(t)*64 + bc*16); \
} while (0)

template<int EPI>  // 0 = bias -> fp32 C;  1 = bias+gelu -> bf16 hi/lo Ch/Cl
__global__ void __launch_bounds__(256, 2)
mma_gemm(const __nv_bfloat16* __restrict__ Ah, const __nv_bfloat16* __restrict__ Al,
         const __nv_bfloat16* __restrict__ Wh, const __nv_bfloat16* __restrict__ Wl,
         const float* __restrict__ bias, float* __restrict__ C,
         __nv_bfloat16* __restrict__ Ch, __nv_bfloat16* __restrict__ Cl,
         int M, int K, int Nc, float scale) {
    extern __shared__ char sm[];
    unsigned sb = smem_u32(sm);
    int tid = threadIdx.x, wid = tid >> 5, lane = tid & 31;
    int g = lane >> 2, q = lane & 3;
    int wm = (wid & 3) * 32, wn = (wid >> 2) * 32;
    int bm0 = blockIdx.y * 128, bn0 = blockIdx.x * 64;

    unsigned arow = tid >> 1;
    unsigned ac0  = (tid & 1) * 2;
    unsigned brow = tid >> 2;
    unsigned bc   = tid & 3;
    const char* Agh = (const char*)(Ah + (size_t)(bm0 + arow) * K);
    const char* Agl = (const char*)(Al + (size_t)(bm0 + arow) * K);
    const char* Bgh = (const char*)(Wh + (size_t)(bn0 + brow) * K);
    const char* Bgl = (const char*)(Wl + (size_t)(bn0 + brow) * K);

    float acc[2][4][4];
#pragma unroll
    for (int i = 0; i < 2; i++)
#pragma unroll
        for (int j = 0; j < 4; j++)
#pragma unroll
            for (int c = 0; c < 4; c++) acc[i][j][c] = 0.f;

    int ntiles = K >> 5;
    GISSUE(0, 0); CP_COMMIT();
    GISSUE(1, 1); CP_COMMIT();

    for (int t = 0; t < ntiles; t++) {
        CP_WAIT1();
        __syncthreads();
        int tn = t + 2;
        if (tn < ntiles) { int s2 = tn % 3; GISSUE(tn, s2); }
        CP_COMMIT();

        const unsigned* Ahs = (const unsigned*)(sm + (t % 3) * STG);
        const unsigned* Als = Ahs + 2560;
        const unsigned* Bhs = Ahs + 5120;
        const unsigned* Bls = Ahs + 6400;
#pragma unroll
        for (int kk = 0; kk < 2; kk++) {
            int kb = kk * 8;
            unsigned ah[2][4], al[2][4], bh[4][2], bl[4][2];
#pragma unroll
            for (int mt = 0; mt < 2; mt++) {
                int r0 = (wm + mt*16 + g) * RS;
                int r1 = r0 + 8 * RS;
                ah[mt][0] = Ahs[r0 + kb + q];     ah[mt][1] = Ahs[r1 + kb + q];
                ah[mt][2] = Ahs[r0 + kb + q + 4]; ah[mt][3] = Ahs[r1 + kb + q + 4];
                al[mt][0] = Als[r0 + kb + q];     al[mt][1] = Als[r1 + kb + q];
                al[mt][2] = Als[r0 + kb + q + 4]; al[mt][3] = Als[r1 + kb + q + 4];
            }
#pragma unroll
            for (int nt = 0; nt < 4; nt++) {
                int rn = (wn + nt*8 + g) * RS;
                bh[nt][0] = Bhs[rn + kb + q]; bh[nt][1] = Bhs[rn + kb + q + 4];
                bl[nt][0] = Bls[rn + kb + q]; bl[nt][1] = Bls[rn + kb + q + 4];
            }
#pragma unroll
            for (int mt = 0; mt < 2; mt++)
#pragma unroll
                for (int nt = 0; nt < 4; nt++) {
                    MMA_BF16(acc[mt][nt], ah[mt], bh[nt]);
                    MMA_BF16(acc[mt][nt], al[mt], bh[nt]);
                    MMA_BF16(acc[mt][nt], ah[mt], bl[nt]);
                }
        }
    }

#pragma unroll
    for (int mt = 0; mt < 2; mt++) {
#pragma unroll
        for (int nt = 0; nt < 4; nt++) {
            int col = bn0 + wn + nt*8 + 2*q;
            int r0  = bm0 + wm + mt*16 + g;
            float blo = bias[col], bhi = bias[col + 1];
            float v00 = (acc[mt][nt][0] + blo) * scale;
            float v01 = (acc[mt][nt][1] + bhi) * scale;
            float v10 = (acc[mt][nt][2] + blo) * scale;
            float v11 = (acc[mt][nt][3] + bhi) * scale;
            if (EPI == 0) {
                *(float2*)&C[(size_t)r0       * Nc + col] = make_float2(v00, v01);
                *(float2*)&C[(size_t)(r0 + 8) * Nc + col] = make_float2(v10, v11);
            } else {
                v00 = gelu_f(v00); v01 = gelu_f(v01);
                v10 = gelu_f(v10); v11 = gelu_f(v11);
                __nv_bfloat16 h0, l0, h1, l1;
                split_bf(v00, h0, l0); split_bf(v01, h1, l1);
                { __nv_bfloat162 hp; hp.x = h0; hp.y = h1;
                  *(__nv_bfloat162*)&Ch[(size_t)r0 * Nc + col] = hp;
                  __nv_bfloat162 lp; lp.x = l0; lp.y = l1;
                  *(__nv_bfloat162*)&Cl[(size_t)r0 * Nc + col] = lp; }
                split_bf(v10, h0, l0); split_bf(v11, h1, l1);
                { __nv_bfloat162 hp; hp.x = h0; hp.y = h1;
                  *(__nv_bfloat162*)&Ch[(size_t)(r0 + 8) * Nc + col] = hp;
                  __nv_bfloat162 lp; lp.x = l0; lp.y = l1;
                  *(__nv_bfloat162*)&Cl[(size_t)(r0 + 8) * Nc + col] = lp; }
            }
        }
    }
}

// ==================== fused attention: scores+bias+mask+softmax+PV ===========
// One block per (b,h). 256 threads = 8 warps; warp handles 4 rows x 12 groups.
// smem: Kd[24][385] | Vd[24][385] | Qs[384][25] | mask[384]
#define FA_KD   0
#define FA_VD   (24*385)
#define FA_QS   (2*24*385)
#define FA_MK   (2*24*385 + 384*25)
#define FA_SMEM ((2*24*385 + 384*25 + 384) * 4)

__global__ void __launch_bounds__(256, 1)
fattn_k(const float* __restrict__ qkv, const float* __restrict__ bias,
        const int* __restrict__ nt,
        __nv_bfloat16* __restrict__ oh, __nv_bfloat16* __restrict__ ol) {
    extern __shared__ float fs[];
    float* kd = fs + FA_KD;
    float* vd = fs + FA_VD;
    float* qs = fs + FA_QS;
    float* mk = fs + FA_MK;
    int bh = blockIdx.x;
    int b = bh >> 5, h = bh & 31;
    int tid = threadIdx.x, w = tid >> 5, lane = tid & 31;
    const float scaling = 0.20412414523193154f;   // 24^-0.5

    for (int i = tid; i < 384*24; i += 256) {
        int m = i / 24, d = i % 24;
        size_t base = ((size_t)m*B_ + b)*QKV + h*D_ + d;
        qs[m*25 + d]  = qkv[base] * scaling;
        kd[d*385 + m] = qkv[base + E_];
        vd[d*385 + m] = qkv[base + 2*E_];
    }
    for (int i = tid; i < 384; i += 256)
        mk[i] = (nt[b*Nn + i] == 0) ? -1e30f : 0.f;
    __syncthreads();

    for (int g = 0; g < 12; g++) {
        int r0 = g*32 + w*4;
        float sv[4][12];
#pragma unroll
        for (int r = 0; r < 4; r++)
#pragma unroll
            for (int j = 0; j < 12; j++) sv[r][j] = 0.f;

        // ---- QK^T: 4 rows x 12 cols per lane, d-blocked by 6 ----
#pragma unroll
        for (int db = 0; db < 4; db++) {
            float qreg[4][6];
#pragma unroll
            for (int r = 0; r < 4; r++)
#pragma unroll
                for (int dd = 0; dd < 6; dd++)
                    qreg[r][dd] = qs[(r0 + r)*25 + db*6 + dd];
#pragma unroll
            for (int j = 0; j < 12; j++) {
                int m = lane + 32*j;
#pragma unroll
                for (int dd = 0; dd < 6; dd++) {
                    float kv = kd[(db*6 + dd)*385 + m];
#pragma unroll
                    for (int r = 0; r < 4; r++)
                        sv[r][j] = fmaf(qreg[r][dd], kv, sv[r][j]);
                }
            }
        }

        // ---- bias + mask + softmax per row ----
#pragma unroll
        for (int r = 0; r < 4; r++) {
            int n = r0 + r;
            const float* brow = bias + ((size_t)bh*Nn + n)*Nn;
            float mx = -3.4e38f;
#pragma unroll
            for (int j = 0; j < 12; j++) {
                int m = lane + 32*j;
                float val = sv[r][j] + brow[m] + mk[m];
                sv[r][j] = val; mx = fmaxf(mx, val);
            }
            for (int o = 16; o; o >>= 1) mx = fmaxf(mx, __shfl_xor_sync(0xffffffffu, mx, o));
            float sum = 0.f;
#pragma unroll
            for (int j = 0; j < 12; j++) {
                float e = __expf(sv[r][j] - mx); sv[r][j] = e; sum += e;
            }
            for (int o = 16; o; o >>= 1) sum += __shfl_xor_sync(0xffffffffu, sum, o);
            float inv = 1.f / sum;
#pragma unroll
            for (int j = 0; j < 12; j++) sv[r][j] *= inv;
        }

        // ---- PV: acc[4][24] in registers ----
        float acc[4][24];
#pragma unroll
        for (int r = 0; r < 4; r++)
#pragma unroll
            for (int d = 0; d < 24; d++) acc[r][d] = 0.f;
#pragma unroll
        for (int j = 0; j < 12; j++) {
            int m = lane + 32*j;
#pragma unroll
            for (int d = 0; d < 24; d++) {
                float v = vd[d*385 + m];
#pragma unroll
                for (int r = 0; r < 4; r++)
                    acc[r][d] = fmaf(sv[r][j], v, acc[r][d]);
            }
        }

        // ---- cross-lane reduce + write bf16 hi/lo ----
#pragma unroll
        for (int r = 0; r < 4; r++) {
            int n = r0 + r;
            float myv = 0.f;
#pragma unroll
            for (int d = 0; d < 24; d++) {
                float t = acc[r][d];
                for (int o = 16; o; o >>= 1) t += __shfl_xor_sync(0xffffffffu, t, o);
                if (lane == d) myv = t;
            }
            if (lane < 24) {
                size_t idx = ((size_t)n*B_ + b)*E_ + h*D_ + lane;
                __nv_bfloat16 hv, lv; split_bf(myv, hv, lv);
                oh[idx] = hv; ol[idx] = lv;
            }
        }
    }
}

// ==================== residual add + LayerNorm (+ bf16 hi/lo out) ============
__global__ void __launch_bounds__(256)
ln_k(const float* __restrict__ x, const float* __restrict__ a,
     const float* __restrict__ s, const float* __restrict__ bb,
     float* __restrict__ out,
     __nv_bfloat16* __restrict__ oh, __nv_bfloat16* __restrict__ ol) {
    __shared__ float r1[8], r2[8];
    int t = blockIdx.x, tid = threadIdx.x;
    const float* xp = x + (size_t)t * E_;
    const float* ap = a + (size_t)t * E_;
    float v[3]; float sum = 0.f;
#pragma unroll
    for (int i = 0; i < 3; i++) { int e = tid + (i << 8); v[i] = xp[e] + ap[e]; sum += v[i]; }
    for (int o = 16; o; o >>= 1) sum += __shfl_xor_sync(0xffffffffu, sum, o);
    if ((tid & 31) == 0) r1[tid >> 5] = sum;
    __syncthreads();
    sum = 0.f;
#pragma unroll
    for (int w = 0; w < 8; w++) sum += r1[w];
    float mu = sum * (1.f / 768.f);
    float var = 0.f;
#pragma unroll
    for (int i = 0; i < 3; i++) { float d = v[i] - mu; var += d * d; }
    for (int o = 16; o; o >>= 1) var += __shfl_xor_sync(0xffffffffu, var, o);
    if ((tid & 31) == 0) r2[tid >> 5] = var;
    __syncthreads();
    var = 0.f;
#pragma unroll
    for (int w = 0; w < 8; w++) var += r2[w];
    float rstd = rsqrtf(var * (1.f / 768.f) + 1e-5f);
#pragma unroll
    for (int i = 0; i < 3; i++) {
        int e = tid + (i << 8);
        float o = (v[i] - mu) * rstd * s[e] + bb[e];
        out[(size_t)t * E_ + e] = o;
        __nv_bfloat16 hh, ll; split_bf(o, hh, ll);
        oh[(size_t)t * E_ + e] = hh; ol[(size_t)t * E_ + e] = ll;
    }
}

// ==================== orchestration ====================
extern "C" void kernel_launch(void* const* d_in, const int* in_sizes, int n_in,
                              void* d_out, int out_size) {
    const int*   nt    = (const int*)  d_in[0];
    const float* nif   = (const float*)d_in[1];
    const int*   ind   = (const int*)  d_in[2];
    const int*   outd  = (const int*)  d_in[3];
    const float* ab    = (const float*)d_in[4];
    const int*   sp    = (const int*)  d_in[5];
    const float* nemb  = (const float*)d_in[6];
    const float* iemb  = (const float*)d_in[7];
    const float* oemb  = (const float*)d_in[8];
    const float* se    = (const float*)d_in[9];
    const float* ser   = (const float*)d_in[10];
    const float* Wq    = (const float*)d_in[11];
    const float* bq    = (const float*)d_in[12];
    const float* Wk    = (const float*)d_in[13];
    const float* bk    = (const float*)d_in[14];
    const float* Wv    = (const float*)d_in[15];
    const float* bv    = (const float*)d_in[16];
    const float* Wo    = (const float*)d_in[17];
    const float* bo    = (const float*)d_in[18];
    const float* W1    = (const float*)d_in[19];
    const float* b1    = (const float*)d_in[20];
    const float* W2    = (const float*)d_in[21];
    const float* b2    = (const float*)d_in[22];
    const float* ln1s  = (const float*)d_in[23];
    const float* ln1b  = (const float*)d_in[24];
    const float* ln2s  = (const float*)d_in[25];
    const float* ln2b  = (const float*)d_in[26];
    float* out = (float*)d_out;

    float *x, *tmp, *qkv, *bias, *bqkv;
    __nv_bfloat16 *xh, *xl, *ch, *cl, *hh, *hl;
    __nv_bfloat16 *wqkvh, *wqkvl, *woh, *wol, *w1h, *w1l, *w2h, *w2l;
    cudaGetSymbolAddress((void**)&x,    g_x);
    cudaGetSymbolAddress((void**)&tmp,  g_tmp);
    cudaGetSymbolAddress((void**)&qkv,  g_qkv);
    cudaGetSymbolAddress((void**)&bias, g_bias);
    cudaGetSymbolAddress((void**)&bqkv, g_bqkv);
    cudaGetSymbolAddress((void**)&xh,   g_xh);
    cudaGetSymbolAddress((void**)&xl,   g_xl);
    cudaGetSymbolAddress((void**)&ch,   g_ch);
    cudaGetSymbolAddress((void**)&cl,   g_cl);
    cudaGetSymbolAddress((void**)&hh,   g_hh);
    cudaGetSymbolAddress((void**)&hl,   g_hl);
    cudaGetSymbolAddress((void**)&wqkvh, g_wqkvh);
    cudaGetSymbolAddress((void**)&wqkvl, g_wqkvl);
    cudaGetSymbolAddress((void**)&woh,   g_woh);
    cudaGetSymbolAddress((void**)&wol,   g_wol);
    cudaGetSymbolAddress((void**)&w1h,   g_w1h);
    cudaGetSymbolAddress((void**)&w1l,   g_w1l);
    cudaGetSymbolAddress((void**)&w2h,   g_w2h);
    cudaGetSymbolAddress((void**)&w2l,   g_w2l);

    cudaFuncSetAttribute(mma_gemm<0>, cudaFuncAttributeMaxDynamicSharedMemorySize, GSMT);
    cudaFuncSetAttribute(mma_gemm<1>, cudaFuncAttributeMaxDynamicSharedMemorySize, GSMT);
    cudaFuncSetAttribute(fattn_k, cudaFuncAttributeMaxDynamicSharedMemorySize, FA_SMEM);

    // ---- prepass ----
    tr_k<<<dim3(E_/32, E_/32, L_), 256>>>(Wq, wqkvh, wqkvl, E_, E_,
        (size_t)E_*E_, (size_t)QKV*E_, 0);
    tr_k<<<dim3(E_/32, E_/32, L_), 256>>>(Wk, wqkvh, wqkvl, E_, E_,
        (size_t)E_*E_, (size_t)QKV*E_, E_);
    tr_k<<<dim3(E_/32, E_/32, L_), 256>>>(Wv, wqkvh, wqkvl, E_, E_,
        (size_t)E_*E_, (size_t)QKV*E_, 2*E_);
    tr_k<<<dim3(E_/32, E_/32, L_), 256>>>(Wo, woh, wol, E_, E_,
        (size_t)E_*E_, (size_t)E_*E_, 0);
    tr_k<<<dim3(F_/32, E_/32, L_), 256>>>(W1, w1h, w1l, E_, F_,
        (size_t)E_*F_, (size_t)F_*E_, 0);
    tr_k<<<dim3(E_/32, F_/32, L_), 256>>>(W2, w2h, w2l, F_, E_,
        (size_t)F_*E_, (size_t)E_*F_, 0);
    packb_k<<<(L_*QKV + 255)/256, 256>>>(bq, bk, bv, bqkv);

    embed_k<<<(T_*E_ + 255)/256, 256>>>(nt, nif, ind, outd, nemb, iemb, oemb, x, xh, xl);
    bias_k<<<dim3(B_, Nn/32, Nn/32), 256>>>(sp, ab, se, ser, bias);

    dim3 gQKV(QKV/64, T_/128);     // (36, 12)
    dim3 gE(E_/64, T_/128);        // (12, 12)
    dim3 gF1(F_/64, T_/128);       // (48, 12)

    for (int l = 0; l < L_; l++) {
        mma_gemm<0><<<gQKV, 256, GSMT>>>(xh, xl,
            wqkvh + (size_t)l*QKV*E_, wqkvl + (size_t)l*QKV*E_,
            bqkv + l*QKV, qkv, hh, hl, T_, E_, QKV, 1.f);

        fattn_k<<<B_*H_, 256, FA_SMEM>>>(qkv, bias, nt, ch, cl);

        mma_gemm<0><<<gE, 256, GSMT>>>(ch, cl,
            woh + (size_t)l*E_*E_, wol + (size_t)l*E_*E_,
            bo + l*E_, tmp, hh, hl, T_, E_, E_, 1.f);
        ln_k<<<T_, 256>>>(x, tmp, ln1s + l*E_, ln1b + l*E_, x, xh, xl);

        mma_gemm<1><<<gF1, 256, GSMT>>>(xh, xl,
            w1h + (size_t)l*F_*E_, w1l + (size_t)l*F_*E_,
            b1 + l*F_, tmp, hh, hl, T_, E_, F_, 1.f);
        mma_gemm<0><<<gE, 256, GSMT>>>(hh, hl,
            w2h + (size_t)l*E_*F_, w2l + (size_t)l*E_*F_,
            b2 + l*E_, tmp, hh, hl, T_, F_, E_, 1.f);

        float* dst = (l == L_-1) ? out : x;
        ln_k<<<T_, 256>>>(x, tmp, ln2s + l*E_, ln2b + l*E_, dst, xh, xl);
    }
}

// round 9
// speedup vs baseline: 1.2623x; 1.0328x over previous
#include <cuda_runtime.h>
#include <cuda_bf16.h>
#include <math.h>

#define B_  4
#define Nn  384
#define E_  768
#define H_  32
#define F_  3072
#define L_  12
#define S_  512
#define D_  24
#define T_  (B_*Nn)          // 1536 tokens
#define QKV 2304             // 3*E

// -------------------- scratch (static device allocations) --------------------
__device__ float g_x   [T_*E_];
__device__ float g_tmp [T_*E_];
__device__ float g_qkv [T_*QKV];
__device__ float g_bias[B_*H_*Nn*Nn];
__device__ float g_bqkv[L_*QKV];
// bf16 hi/lo activation buffers
__device__ __nv_bfloat16 g_xh[T_*E_],  g_xl[T_*E_];
__device__ __nv_bfloat16 g_ch[T_*E_],  g_cl[T_*E_];
__device__ __nv_bfloat16 g_hh[T_*F_],  g_hl[T_*F_];
// bf16 hi/lo transposed weights, [l][n][k]
__device__ __nv_bfloat16 g_wqkvh[(size_t)L_*QKV*E_], g_wqkvl[(size_t)L_*QKV*E_];
__device__ __nv_bfloat16 g_woh  [(size_t)L_*E_*E_],  g_wol  [(size_t)L_*E_*E_];
__device__ __nv_bfloat16 g_w1h  [(size_t)L_*F_*E_],  g_w1l  [(size_t)L_*F_*E_];
__device__ __nv_bfloat16 g_w2h  [(size_t)L_*E_*F_],  g_w2l  [(size_t)L_*E_*F_];

// ==================== helpers ====================
__device__ __forceinline__ float gelu_f(float x) {
    return 0.5f * x * (1.0f + tanhf(0.7978845608028654f * (x + 0.044715f * x * x * x)));
}
__device__ __forceinline__ unsigned smem_u32(const void* p) {
    return (unsigned)__cvta_generic_to_shared(p);
}
#define CP_ASYNC16(dst, src) \
    asm volatile("cp.async.cg.shared.global [%0], [%1], 16;\n" :: "r"(dst), "l"(src) : "memory")
#define CP_COMMIT() asm volatile("cp.async.commit_group;\n" ::: "memory")
#define CP_WAIT1()  asm volatile("cp.async.wait_group 1;\n" ::: "memory")

#define MMA_BF16(acc, a, b) \
    asm volatile("mma.sync.aligned.m16n8k16.row.col.f32.bf16.bf16.f32 " \
        "{%0,%1,%2,%3}, {%4,%5,%6,%7}, {%8,%9}, {%0,%1,%2,%3};" \
        : "+f"((acc)[0]), "+f"((acc)[1]), "+f"((acc)[2]), "+f"((acc)[3]) \
        : "r"((a)[0]), "r"((a)[1]), "r"((a)[2]), "r"((a)[3]), "r"((b)[0]), "r"((b)[1]))

#define LDMX4(r0, r1, r2, r3, addr) \
    asm volatile("ldmatrix.sync.aligned.m8n8.x4.shared.b16 {%0,%1,%2,%3}, [%4];" \
        : "=r"(r0), "=r"(r1), "=r"(r2), "=r"(r3) : "r"(addr))

__device__ __forceinline__ void split_bf(float v, __nv_bfloat16& h, __nv_bfloat16& l) {
    h = __float2bfloat16_rn(v);
    l = __float2bfloat16_rn(v - __bfloat162float(h));
}

// ==================== weight transpose + bf16 split ====================
__global__ void __launch_bounds__(256)
tr_k(const float* __restrict__ src, __nv_bfloat16* __restrict__ dh,
     __nv_bfloat16* __restrict__ dl, int K, int N,
     size_t sLs, size_t dLs, int ro) {
    __shared__ float tile[32][33];
    int l = blockIdx.z;
    int n0 = blockIdx.x * 32, k0 = blockIdx.y * 32;
    int tx = threadIdx.x & 31, ty = threadIdx.x >> 5;
    const float* s = src + (size_t)l * sLs;
#pragma unroll
    for (int r = 0; r < 4; r++)
        tile[ty + r*8][tx] = s[(size_t)(k0 + ty + r*8) * N + n0 + tx];
    __syncthreads();
#pragma unroll
    for (int r = 0; r < 4; r++) {
        int n = n0 + ty + r*8, k = k0 + tx;
        float v = tile[tx][ty + r*8];
        __nv_bfloat16 h, lo; split_bf(v, h, lo);
        size_t di = (size_t)l * dLs + (size_t)(ro + n) * K + k;
        dh[di] = h; dl[di] = lo;
    }
}
__global__ void packb_k(const float* __restrict__ bq, const float* __restrict__ bk,
                        const float* __restrict__ bv, float* __restrict__ bo) {
    int idx = blockIdx.x * blockDim.x + threadIdx.x;
    if (idx >= L_*QKV) return;
    int n = idx % QKV, l = idx / QKV;
    float v;
    if      (n < E_)   v = bq[l*E_ + n];
    else if (n < 2*E_) v = bk[l*E_ + n - E_];
    else               v = bv[l*E_ + n - 2*E_];
    bo[idx] = v;
}

// ==================== embedding (fp32 + bf16 hi/lo) ====================
__global__ void embed_k(const int* __restrict__ nt, const float* __restrict__ nif,
                        const int* __restrict__ ind, const int* __restrict__ outd,
                        const float* __restrict__ nemb, const float* __restrict__ iemb,
                        const float* __restrict__ oemb, float* __restrict__ x,
                        __nv_bfloat16* __restrict__ xh, __nv_bfloat16* __restrict__ xl) {
    int idx = blockIdx.x * blockDim.x + threadIdx.x;
    if (idx >= T_*E_) return;
    int e = idx % E_, tok = idx / E_;
    int b = tok % B_, n = tok / B_;
    int bn = b*Nn + n;
    int t  = nt[bn];
    float v = nemb[t*E_+e] + iemb[ind[bn]*E_+e] + oemb[outd[bn]*E_+e] + nif[(size_t)bn*E_+e];
    x[idx] = v;
    __nv_bfloat16 h, lo; split_bf(v, h, lo);
    xh[idx] = h; xl[idx] = lo;
}

// ==================== spatial bias (tiled) ====================
__global__ void __launch_bounds__(256)
bias_k(const int* __restrict__ sp, const float* __restrict__ ab,
       const float* __restrict__ se, const float* __restrict__ ser,
       float* __restrict__ bias) {
    int b = blockIdx.x, n0 = blockIdx.y * 32, m0 = blockIdx.z * 32;
    __shared__ int s1t[32][33];
    __shared__ int s2t[32][33];
    __shared__ float abt[32][33];
    int tid = threadIdx.x;
    for (int i = tid; i < 1024; i += 256) {
        int r = i >> 5, cc = i & 31;
        s1t[r][cc] = sp[((size_t)(b*Nn) + n0 + r) * Nn + m0 + cc];
        s2t[r][cc] = sp[((size_t)(b*Nn) + m0 + r) * Nn + n0 + cc];
        abt[r][cc] = ab[((size_t)(b*Nn) + n0 + r) * Nn + m0 + cc];
    }
    __syncthreads();
    for (int h = 0; h < H_; h++) {
        for (int i = tid; i < 1024; i += 256) {
            int r = i >> 5, cc = i & 31;
            float v = se[s1t[r][cc] * H_ + h] + ser[s2t[cc][r] * H_ + h] + abt[r][cc];
            bias[(((size_t)(b*H_ + h) * Nn) + n0 + r) * Nn + m0 + cc] = v;
        }
    }
}

// ==================== bf16x3 tensor-core GEMM (mma.sync + ldmatrix) ==========
#define RS   20
#define STG  30720
#define GSMT (3*STG)

#define GISSUE(t, s) do { \
    unsigned so_ = sb + (unsigned)(s)*STG; \
    unsigned da_ = so_ + arow*80u + ac0*16u; \
    const char* gah_ = Agh + (size_t)(t)*64 + ac0*16; \
    const char* gal_ = Agl + (size_t)(t)*64 + ac0*16; \
    CP_ASYNC16(da_, gah_); CP_ASYNC16(da_+16u, gah_+16); \
    CP_ASYNC16(da_+10240u, gal_); CP_ASYNC16(da_+10256u, gal_+16); \
    unsigned db_ = so_ + 20480u + brow*80u + bc*16u; \
    CP_ASYNC16(db_, Bgh + (size_t)(t)*64 + bc*16); \
    CP_ASYNC16(db_+5120u, Bgl + (size_t)(t)*64 + bc*16); \
} while (0)

template<int EPI>  // 0 = bias -> fp32 C;  1 = bias+gelu -> bf16 hi/lo Ch/Cl
__global__ void __launch_bounds__(256, 2)
mma_gemm(const __nv_bfloat16* __restrict__ Ah, const __nv_bfloat16* __restrict__ Al,
         const __nv_bfloat16* __restrict__ Wh, const __nv_bfloat16* __restrict__ Wl,
         const float* __restrict__ bias, float* __restrict__ C,
         __nv_bfloat16* __restrict__ Ch, __nv_bfloat16* __restrict__ Cl,
         int M, int K, int Nc, float scale) {
    extern __shared__ char sm[];
    unsigned sb = smem_u32(sm);
    int tid = threadIdx.x, wid = tid >> 5, lane = tid & 31;
    int q = lane & 3;
    int wm = (wid & 3) * 32, wn = (wid >> 2) * 32;
    int bm0 = blockIdx.y * 128, bn0 = blockIdx.x * 64;

    // cp.async producer mapping
    unsigned arow = tid >> 1;
    unsigned ac0  = (tid & 1) * 2;
    unsigned brow = tid >> 2;
    unsigned bc   = tid & 3;
    const char* Agh = (const char*)(Ah + (size_t)(bm0 + arow) * K);
    const char* Agl = (const char*)(Al + (size_t)(bm0 + arow) * K);
    const char* Bgh = (const char*)(Wh + (size_t)(bn0 + brow) * K);
    const char* Bgl = (const char*)(Wl + (size_t)(bn0 + brow) * K);

    // ldmatrix per-lane address offsets (relative to stage base)
    unsigned lsub = (unsigned)lane >> 3, lr = (unsigned)lane & 7;
    // A x4: m0=rows 0-7 kLo, m1=rows 8-15 kLo, m2=rows 0-7 kHi, m3=rows 8-15 kHi
    unsigned aoff = ((unsigned)wm + (lsub & 1) * 8 + lr) * 80u + (lsub >> 1) * 16u;
    // B x4: m0=n-rows 0-7 kLo, m1=rows 0-7 kHi, m2=rows 8-15 kLo, m3=rows 8-15 kHi
    unsigned boff = 20480u + ((unsigned)wn + (lsub >> 1) * 8 + lr) * 80u + (lsub & 1) * 16u;

    float acc[2][4][4];
#pragma unroll
    for (int i = 0; i < 2; i++)
#pragma unroll
        for (int j = 0; j < 4; j++)
#pragma unroll
            for (int c = 0; c < 4; c++) acc[i][j][c] = 0.f;

    int ntiles = K >> 5;
    GISSUE(0, 0); CP_COMMIT();
    GISSUE(1, 1); CP_COMMIT();

    for (int t = 0; t < ntiles; t++) {
        CP_WAIT1();
        __syncthreads();
        int tn = t + 2;
        if (tn < ntiles) { int s2 = tn % 3; GISSUE(tn, s2); }
        CP_COMMIT();

        unsigned stg = sb + (unsigned)(t % 3) * STG;
        unsigned aH = stg + aoff;            // A hi
        unsigned bH = stg + boff;            // B hi
#pragma unroll
        for (int kk = 0; kk < 2; kk++) {
            unsigned ko = (unsigned)kk * 32u;
            unsigned ah[2][4], al[2][4], bh[4][2], bl[4][2];
#pragma unroll
            for (int mt = 0; mt < 2; mt++) {
                unsigned a0 = aH + (unsigned)mt * 1280u + ko;
                LDMX4(ah[mt][0], ah[mt][1], ah[mt][2], ah[mt][3], a0);
                LDMX4(al[mt][0], al[mt][1], al[mt][2], al[mt][3], a0 + 10240u);
            }
#pragma unroll
            for (int np = 0; np < 2; np++) {
                unsigned b0 = bH + (unsigned)np * 1280u + ko;
                LDMX4(bh[2*np][0], bh[2*np][1], bh[2*np+1][0], bh[2*np+1][1], b0);
                LDMX4(bl[2*np][0], bl[2*np][1], bl[2*np+1][0], bl[2*np+1][1], b0 + 5120u);
            }
#pragma unroll
            for (int mt = 0; mt < 2; mt++)
#pragma unroll
                for (int nt = 0; nt < 4; nt++) {
                    MMA_BF16(acc[mt][nt], ah[mt], bh[nt]);
                    MMA_BF16(acc[mt][nt], al[mt], bh[nt]);
                    MMA_BF16(acc[mt][nt], ah[mt], bl[nt]);
                }
        }
    }

    int g = lane >> 2;
#pragma unroll
    for (int mt = 0; mt < 2; mt++) {
#pragma unroll
        for (int nt = 0; nt < 4; nt++) {
            int col = bn0 + wn + nt*8 + 2*q;
            int r0  = bm0 + wm + mt*16 + g;
            float blo = bias[col], bhi = bias[col + 1];
            float v00 = (acc[mt][nt][0] + blo) * scale;
            float v01 = (acc[mt][nt][1] + bhi) * scale;
            float v10 = (acc[mt][nt][2] + blo) * scale;
            float v11 = (acc[mt][nt][3] + bhi) * scale;
            if (EPI == 0) {
                *(float2*)&C[(size_t)r0       * Nc + col] = make_float2(v00, v01);
                *(float2*)&C[(size_t)(r0 + 8) * Nc + col] = make_float2(v10, v11);
            } else {
                v00 = gelu_f(v00); v01 = gelu_f(v01);
                v10 = gelu_f(v10); v11 = gelu_f(v11);
                __nv_bfloat16 h0, l0, h1, l1;
                split_bf(v00, h0, l0); split_bf(v01, h1, l1);
                { __nv_bfloat162 hp; hp.x = h0; hp.y = h1;
                  *(__nv_bfloat162*)&Ch[(size_t)r0 * Nc + col] = hp;
                  __nv_bfloat162 lp; lp.x = l0; lp.y = l1;
                  *(__nv_bfloat162*)&Cl[(size_t)r0 * Nc + col] = lp; }
                split_bf(v10, h0, l0); split_bf(v11, h1, l1);
                { __nv_bfloat162 hp; hp.x = h0; hp.y = h1;
                  *(__nv_bfloat162*)&Ch[(size_t)(r0 + 8) * Nc + col] = hp;
                  __nv_bfloat162 lp; lp.x = l0; lp.y = l1;
                  *(__nv_bfloat162*)&Cl[(size_t)(r0 + 8) * Nc + col] = lp; }
            }
        }
    }
}

// ==================== fused attention: scores+bias+mask+softmax+PV ===========
#define FA_KD   0
#define FA_VD   (24*385)
#define FA_QS   (2*24*385)
#define FA_MK   (2*24*385 + 384*25)
#define FA_SMEM ((2*24*385 + 384*25 + 384) * 4)

__global__ void __launch_bounds__(256, 1)
fattn_k(const float* __restrict__ qkv, const float* __restrict__ bias,
        const int* __restrict__ nt,
        __nv_bfloat16* __restrict__ oh, __nv_bfloat16* __restrict__ ol) {
    extern __shared__ float fs[];
    float* kd = fs + FA_KD;
    float* vd = fs + FA_VD;
    float* qs = fs + FA_QS;
    float* mk = fs + FA_MK;
    int bh = blockIdx.x;
    int b = bh >> 5, h = bh & 31;
    int tid = threadIdx.x, w = tid >> 5, lane = tid & 31;
    const float scaling = 0.20412414523193154f;   // 24^-0.5

    for (int i = tid; i < 384*24; i += 256) {
        int m = i / 24, d = i % 24;
        size_t base = ((size_t)m*B_ + b)*QKV + h*D_ + d;
        qs[m*25 + d]  = qkv[base] * scaling;
        kd[d*385 + m] = qkv[base + E_];
        vd[d*385 + m] = qkv[base + 2*E_];
    }
    for (int i = tid; i < 384; i += 256)
        mk[i] = (nt[b*Nn + i] == 0) ? -1e30f : 0.f;
    __syncthreads();

    for (int g = 0; g < 12; g++) {
        int r0 = g*32 + w*4;
        float sv[4][12];
#pragma unroll
        for (int r = 0; r < 4; r++)
#pragma unroll
            for (int j = 0; j < 12; j++) sv[r][j] = 0.f;

#pragma unroll
        for (int db = 0; db < 4; db++) {
            float qreg[4][6];
#pragma unroll
            for (int r = 0; r < 4; r++)
#pragma unroll
                for (int dd = 0; dd < 6; dd++)
                    qreg[r][dd] = qs[(r0 + r)*25 + db*6 + dd];
#pragma unroll
            for (int j = 0; j < 12; j++) {
                int m = lane + 32*j;
#pragma unroll
                for (int dd = 0; dd < 6; dd++) {
                    float kv = kd[(db*6 + dd)*385 + m];
#pragma unroll
                    for (int r = 0; r < 4; r++)
                        sv[r][j] = fmaf(qreg[r][dd], kv, sv[r][j]);
                }
            }
        }

#pragma unroll
        for (int r = 0; r < 4; r++) {
            int n = r0 + r;
            const float* brow = bias + ((size_t)bh*Nn + n)*Nn;
            float mx = -3.4e38f;
#pragma unroll
            for (int j = 0; j < 12; j++) {
                int m = lane + 32*j;
                float val = sv[r][j] + brow[m] + mk[m];
                sv[r][j] = val; mx = fmaxf(mx, val);
            }
            for (int o = 16; o; o >>= 1) mx = fmaxf(mx, __shfl_xor_sync(0xffffffffu, mx, o));
            float sum = 0.f;
#pragma unroll
            for (int j = 0; j < 12; j++) {
                float e = __expf(sv[r][j] - mx); sv[r][j] = e; sum += e;
            }
            for (int o = 16; o; o >>= 1) sum += __shfl_xor_sync(0xffffffffu, sum, o);
            float inv = 1.f / sum;
#pragma unroll
            for (int j = 0; j < 12; j++) sv[r][j] *= inv;
        }

        float acc[4][24];
#pragma unroll
        for (int r = 0; r < 4; r++)
#pragma unroll
            for (int d = 0; d < 24; d++) acc[r][d] = 0.f;
#pragma unroll
        for (int j = 0; j < 12; j++) {
            int m = lane + 32*j;
#pragma unroll
            for (int d = 0; d < 24; d++) {
                float v = vd[d*385 + m];
#pragma unroll
                for (int r = 0; r < 4; r++)
                    acc[r][d] = fmaf(sv[r][j], v, acc[r][d]);
            }
        }

#pragma unroll
        for (int r = 0; r < 4; r++) {
            int n = r0 + r;
            float myv = 0.f;
#pragma unroll
            for (int d = 0; d < 24; d++) {
                float t = acc[r][d];
                for (int o = 16; o; o >>= 1) t += __shfl_xor_sync(0xffffffffu, t, o);
                if (lane == d) myv = t;
            }
            if (lane < 24) {
                size_t idx = ((size_t)n*B_ + b)*E_ + h*D_ + lane;
                __nv_bfloat16 hv, lv; split_bf(myv, hv, lv);
                oh[idx] = hv; ol[idx] = lv;
            }
        }
    }
}

// ==================== residual add + LayerNorm (+ bf16 hi/lo out) ============
__global__ void __launch_bounds__(256)
ln_k(const float* __restrict__ x, const float* __restrict__ a,
     const float* __restrict__ s, const float* __restrict__ bb,
     float* __restrict__ out,
     __nv_bfloat16* __restrict__ oh, __nv_bfloat16* __restrict__ ol) {
    __shared__ float r1[8], r2[8];
    int t = blockIdx.x, tid = threadIdx.x;
    const float* xp = x + (size_t)t * E_;
    const float* ap = a + (size_t)t * E_;
    float v[3]; float sum = 0.f;
#pragma unroll
    for (int i = 0; i < 3; i++) { int e = tid + (i << 8); v[i] = xp[e] + ap[e]; sum += v[i]; }
    for (int o = 16; o; o >>= 1) sum += __shfl_xor_sync(0xffffffffu, sum, o);
    if ((tid & 31) == 0) r1[tid >> 5] = sum;
    __syncthreads();
    sum = 0.f;
#pragma unroll
    for (int w = 0; w < 8; w++) sum += r1[w];
    float mu = sum * (1.f / 768.f);
    float var = 0.f;
#pragma unroll
    for (int i = 0; i < 3; i++) { float d = v[i] - mu; var += d * d; }
    for (int o = 16; o; o >>= 1) var += __shfl_xor_sync(0xffffffffu, var, o);
    if ((tid & 31) == 0) r2[tid >> 5] = var;
    __syncthreads();
    var = 0.f;
#pragma unroll
    for (int w = 0; w < 8; w++) var += r2[w];
    float rstd = rsqrtf(var * (1.f / 768.f) + 1e-5f);
#pragma unroll
    for (int i = 0; i < 3; i++) {
        int e = tid + (i << 8);
        float o = (v[i] - mu) * rstd * s[e] + bb[e];
        out[(size_t)t * E_ + e] = o;
        __nv_bfloat16 hh, ll; split_bf(o, hh, ll);
        oh[(size_t)t * E_ + e] = hh; ol[(size_t)t * E_ + e] = ll;
    }
}

// ==================== orchestration ====================
extern "C" void kernel_launch(void* const* d_in, const int* in_sizes, int n_in,
                              void* d_out, int out_size) {
    const int*   nt    = (const int*)  d_in[0];
    const float* nif   = (const float*)d_in[1];
    const int*   ind   = (const int*)  d_in[2];
    const int*   outd  = (const int*)  d_in[3];
    const float* ab    = (const float*)d_in[4];
    const int*   sp    = (const int*)  d_in[5];
    const float* nemb  = (const float*)d_in[6];
    const float* iemb  = (const float*)d_in[7];
    const float* oemb  = (const float*)d_in[8];
    const float* se    = (const float*)d_in[9];
    const float* ser   = (const float*)d_in[10];
    const float* Wq    = (const float*)d_in[11];
    const float* bq    = (const float*)d_in[12];
    const float* Wk    = (const float*)d_in[13];
    const float* bk    = (const float*)d_in[14];
    const float* Wv    = (const float*)d_in[15];
    const float* bv    = (const float*)d_in[16];
    const float* Wo    = (const float*)d_in[17];
    const float* bo    = (const float*)d_in[18];
    const float* W1    = (const float*)d_in[19];
    const float* b1    = (const float*)d_in[20];
    const float* W2    = (const float*)d_in[21];
    const float* b2    = (const float*)d_in[22];
    const float* ln1s  = (const float*)d_in[23];
    const float* ln1b  = (const float*)d_in[24];
    const float* ln2s  = (const float*)d_in[25];
    const float* ln2b  = (const float*)d_in[26];
    float* out = (float*)d_out;

    float *x, *tmp, *qkv, *bias, *bqkv;
    __nv_bfloat16 *xh, *xl, *ch, *cl, *hh, *hl;
    __nv_bfloat16 *wqkvh, *wqkvl, *woh, *wol, *w1h, *w1l, *w2h, *w2l;
    cudaGetSymbolAddress((void**)&x,    g_x);
    cudaGetSymbolAddress((void**)&tmp,  g_tmp);
    cudaGetSymbolAddress((void**)&qkv,  g_qkv);
    cudaGetSymbolAddress((void**)&bias, g_bias);
    cudaGetSymbolAddress((void**)&bqkv, g_bqkv);
    cudaGetSymbolAddress((void**)&xh,   g_xh);
    cudaGetSymbolAddress((void**)&xl,   g_xl);
    cudaGetSymbolAddress((void**)&ch,   g_ch);
    cudaGetSymbolAddress((void**)&cl,   g_cl);
    cudaGetSymbolAddress((void**)&hh,   g_hh);
    cudaGetSymbolAddress((void**)&hl,   g_hl);
    cudaGetSymbolAddress((void**)&wqkvh, g_wqkvh);
    cudaGetSymbolAddress((void**)&wqkvl, g_wqkvl);
    cudaGetSymbolAddress((void**)&woh,   g_woh);
    cudaGetSymbolAddress((void**)&wol,   g_wol);
    cudaGetSymbolAddress((void**)&w1h,   g_w1h);
    cudaGetSymbolAddress((void**)&w1l,   g_w1l);
    cudaGetSymbolAddress((void**)&w2h,   g_w2h);
    cudaGetSymbolAddress((void**)&w2l,   g_w2l);

    cudaFuncSetAttribute(mma_gemm<0>, cudaFuncAttributeMaxDynamicSharedMemorySize, GSMT);
    cudaFuncSetAttribute(mma_gemm<1>, cudaFuncAttributeMaxDynamicSharedMemorySize, GSMT);
    cudaFuncSetAttribute(fattn_k, cudaFuncAttributeMaxDynamicSharedMemorySize, FA_SMEM);

    // ---- prepass ----
    tr_k<<<dim3(E_/32, E_/32, L_), 256>>>(Wq, wqkvh, wqkvl, E_, E_,
        (size_t)E_*E_, (size_t)QKV*E_, 0);
    tr_k<<<dim3(E_/32, E_/32, L_), 256>>>(Wk, wqkvh, wqkvl, E_, E_,
        (size_t)E_*E_, (size_t)QKV*E_, E_);
    tr_k<<<dim3(E_/32, E_/32, L_), 256>>>(Wv, wqkvh, wqkvl, E_, E_,
        (size_t)E_*E_, (size_t)QKV*E_, 2*E_);
    tr_k<<<dim3(E_/32, E_/32, L_), 256>>>(Wo, woh, wol, E_, E_,
        (size_t)E_*E_, (size_t)E_*E_, 0);
    tr_k<<<dim3(F_/32, E_/32, L_), 256>>>(W1, w1h, w1l, E_, F_,
        (size_t)E_*F_, (size_t)F_*E_, 0);
    tr_k<<<dim3(E_/32, F_/32, L_), 256>>>(W2, w2h, w2l, F_, E_,
        (size_t)F_*E_, (size_t)E_*F_, 0);
    packb_k<<<(L_*QKV + 255)/256, 256>>>(bq, bk, bv, bqkv);

    embed_k<<<(T_*E_ + 255)/256, 256>>>(nt, nif, ind, outd, nemb, iemb, oemb, x, xh, xl);
    bias_k<<<dim3(B_, Nn/32, Nn/32), 256>>>(sp, ab, se, ser, bias);

    dim3 gQKV(QKV/64, T_/128);     // (36, 12)
    dim3 gE(E_/64, T_/128);        // (12, 12)
    dim3 gF1(F_/64, T_/128);       // (48, 12)

    for (int l = 0; l < L_; l++) {
        mma_gemm<0><<<gQKV, 256, GSMT>>>(xh, xl,
            wqkvh + (size_t)l*QKV*E_, wqkvl + (size_t)l*QKV*E_,
            bqkv + l*QKV, qkv, hh, hl, T_, E_, QKV, 1.f);

        fattn_k<<<B_*H_, 256, FA_SMEM>>>(qkv, bias, nt, ch, cl);

        mma_gemm<0><<<gE, 256, GSMT>>>(ch, cl,
            woh + (size_t)l*E_*E_, wol + (size_t)l*E_*E_,
            bo + l*E_, tmp, hh, hl, T_, E_, E_, 1.f);
        ln_k<<<T_, 256>>>(x, tmp, ln1s + l*E_, ln1b + l*E_, x, xh, xl);

        mma_gemm<1><<<gF1, 256, GSMT>>>(xh, xl,
            w1h + (size_t)l*F_*E_, w1l + (size_t)l*F_*E_,
            b1 + l*F_, tmp, hh, hl, T_, E_, F_, 1.f);
        mma_gemm<0><<<gE, 256, GSMT>>>(hh, hl,
            w2h + (size_t)l*E_*F_, w2l + (size_t)l*E_*F_,
            b2 + l*E_, tmp, hh, hl, T_, F_, E_, 1.f);

        float* dst = (l == L_-1) ? out : x;
        ln_k<<<T_, 256>>>(x, tmp, ln2s + l*E_, ln2b + l*E_, dst, xh, xl);
    }
}

// round 11
// speedup vs baseline: 1.2635x; 1.0009x over previous
#include <cuda_runtime.h>
#include <cuda_bf16.h>
#include <math.h>

#define B_  4
#define Nn  384
#define E_  768
#define H_  32
#define F_  3072
#define L_  12
#define S_  512
#define D_  24
#define T_  (B_*Nn)          // 1536 tokens
#define QKV 2304             // 3*E

// -------------------- scratch (static device allocations) --------------------
__device__ float g_x   [T_*E_];
__device__ float g_tmp [T_*E_];
__device__ float g_qkv [T_*QKV];
__device__ float g_bias[B_*H_*Nn*Nn];
__device__ float g_bqkv[L_*QKV];
// bf16 hi/lo activation buffers
__device__ __nv_bfloat16 g_xh[T_*E_],  g_xl[T_*E_];
__device__ __nv_bfloat16 g_ch[T_*E_],  g_cl[T_*E_];
__device__ __nv_bfloat16 g_hh[T_*F_],  g_hl[T_*F_];
// bf16 hi/lo transposed weights, [l][n][k]
__device__ __nv_bfloat16 g_wqkvh[(size_t)L_*QKV*E_], g_wqkvl[(size_t)L_*QKV*E_];
__device__ __nv_bfloat16 g_woh  [(size_t)L_*E_*E_],  g_wol  [(size_t)L_*E_*E_];
__device__ __nv_bfloat16 g_w1h  [(size_t)L_*F_*E_],  g_w1l  [(size_t)L_*F_*E_];
__device__ __nv_bfloat16 g_w2h  [(size_t)L_*E_*F_],  g_w2l  [(size_t)L_*E_*F_];

// ==================== helpers ====================
__device__ __forceinline__ float gelu_f(float x) {
    return 0.5f * x * (1.0f + tanhf(0.7978845608028654f * (x + 0.044715f * x * x * x)));
}
__device__ __forceinline__ unsigned smem_u32(const void* p) {
    return (unsigned)__cvta_generic_to_shared(p);
}
#define CP_ASYNC16(dst, src) \
    asm volatile("cp.async.cg.shared.global [%0], [%1], 16;\n" :: "r"(dst), "l"(src) : "memory")
#define CP_COMMIT() asm volatile("cp.async.commit_group;\n" ::: "memory")
#define CP_WAIT1()  asm volatile("cp.async.wait_group 1;\n" ::: "memory")

#define MMA_BF16(acc, a, b) \
    asm volatile("mma.sync.aligned.m16n8k16.row.col.f32.bf16.bf16.f32 " \
        "{%0,%1,%2,%3}, {%4,%5,%6,%7}, {%8,%9}, {%0,%1,%2,%3};" \
        : "+f"((acc)[0]), "+f"((acc)[1]), "+f"((acc)[2]), "+f"((acc)[3]) \
        : "r"((a)[0]), "r"((a)[1]), "r"((a)[2]), "r"((a)[3]), "r"((b)[0]), "r"((b)[1]))

#define LDMX4(r0, r1, r2, r3, addr) \
    asm volatile("ldmatrix.sync.aligned.m8n8.x4.shared.b16 {%0,%1,%2,%3}, [%4];" \
        : "=r"(r0), "=r"(r1), "=r"(r2), "=r"(r3) : "r"(addr))

__device__ __forceinline__ void split_bf(float v, __nv_bfloat16& h, __nv_bfloat16& l) {
    h = __float2bfloat16_rn(v);
    l = __float2bfloat16_rn(v - __bfloat162float(h));
}

// ==================== weight transpose + bf16 split ====================
// generic: src fp32 [K][N] row-major per layer -> dst bf16 [N][K] hi/lo
__global__ void __launch_bounds__(256)
tr_k(const float* __restrict__ src, __nv_bfloat16* __restrict__ dh,
     __nv_bfloat16* __restrict__ dl, int K, int N,
     size_t sLs, size_t dLs, int ro) {
    __shared__ float tile[32][33];
    int l = blockIdx.z;
    int n0 = blockIdx.x * 32, k0 = blockIdx.y * 32;
    int tx = threadIdx.x & 31, ty = threadIdx.x >> 5;
    const float* s = src + (size_t)l * sLs;
#pragma unroll
    for (int r = 0; r < 4; r++)
        tile[ty + r*8][tx] = s[(size_t)(k0 + ty + r*8) * N + n0 + tx];
    __syncthreads();
#pragma unroll
    for (int r = 0; r < 4; r++) {
        int n = n0 + ty + r*8, k = k0 + tx;
        float v = tile[tx][ty + r*8];
        __nv_bfloat16 h, lo; split_bf(v, h, lo);
        size_t di = (size_t)l * dLs + (size_t)(ro + n) * K + k;
        dh[di] = h; dl[di] = lo;
    }
}

// fused transpose for the four ExE weights (Wq/Wk/Wv -> wqkv, Wo -> wo)
__global__ void __launch_bounds__(256)
tr4_k(const float* __restrict__ Wq, const float* __restrict__ Wk,
      const float* __restrict__ Wv, const float* __restrict__ Wo,
      __nv_bfloat16* __restrict__ qh, __nv_bfloat16* __restrict__ ql,
      __nv_bfloat16* __restrict__ ohp, __nv_bfloat16* __restrict__ olp) {
    __shared__ float tile[32][33];
    int z = blockIdx.z;
    int which = z / L_, l = z - which * L_;
    const float* src = (which == 0) ? Wq : (which == 1) ? Wk : (which == 2) ? Wv : Wo;
    __nv_bfloat16* dh = (which < 3) ? qh : ohp;
    __nv_bfloat16* dl = (which < 3) ? ql : olp;
    size_t dLs = (which < 3) ? (size_t)QKV*E_ : (size_t)E_*E_;
    int ro = (which < 3) ? which * E_ : 0;

    int n0 = blockIdx.x * 32, k0 = blockIdx.y * 32;
    int tx = threadIdx.x & 31, ty = threadIdx.x >> 5;
    const float* s = src + (size_t)l * E_ * E_;
#pragma unroll
    for (int r = 0; r < 4; r++)
        tile[ty + r*8][tx] = s[(size_t)(k0 + ty + r*8) * E_ + n0 + tx];
    __syncthreads();
#pragma unroll
    for (int r = 0; r < 4; r++) {
        int n = n0 + ty + r*8, k = k0 + tx;
        float v = tile[tx][ty + r*8];
        __nv_bfloat16 h, lo; split_bf(v, h, lo);
        size_t di = (size_t)l * dLs + (size_t)(ro + n) * E_ + k;
        dh[di] = h; dl[di] = lo;
    }
}

// ==================== embedding + packb (merged: 4608 + 108 blocks) ==========
__global__ void embed_packb_k(const int* __restrict__ nt, const float* __restrict__ nif,
                              const int* __restrict__ ind, const int* __restrict__ outd,
                              const float* __restrict__ nemb, const float* __restrict__ iemb,
                              const float* __restrict__ oemb, float* __restrict__ x,
                              __nv_bfloat16* __restrict__ xh, __nv_bfloat16* __restrict__ xl,
                              const float* __restrict__ bq, const float* __restrict__ bk,
                              const float* __restrict__ bv, float* __restrict__ bo) {
    int bid = blockIdx.x;
    if (bid < 4608) {
        int idx = bid * 256 + threadIdx.x;
        int e = idx % E_, tok = idx / E_;
        int b = tok % B_, n = tok / B_;
        int bn = b*Nn + n;
        int t  = nt[bn];
        float v = nemb[t*E_+e] + iemb[ind[bn]*E_+e] + oemb[outd[bn]*E_+e] + nif[(size_t)bn*E_+e];
        x[idx] = v;
        __nv_bfloat16 h, lo; split_bf(v, h, lo);
        xh[idx] = h; xl[idx] = lo;
    } else {
        int idx = (bid - 4608) * 256 + threadIdx.x;
        if (idx >= L_*QKV) return;
        int n = idx % QKV, l = idx / QKV;
        float v;
        if      (n < E_)   v = bq[l*E_ + n];
        else if (n < 2*E_) v = bk[l*E_ + n - E_];
        else               v = bv[l*E_ + n - 2*E_];
        bo[idx] = v;
    }
}

// ==================== spatial bias (tiled) ====================
__global__ void __launch_bounds__(256)
bias_k(const int* __restrict__ sp, const float* __restrict__ ab,
       const float* __restrict__ se, const float* __restrict__ ser,
       float* __restrict__ bias) {
    int b = blockIdx.x, n0 = blockIdx.y * 32, m0 = blockIdx.z * 32;
    __shared__ int s1t[32][33];
    __shared__ int s2t[32][33];
    __shared__ float abt[32][33];
    int tid = threadIdx.x;
    for (int i = tid; i < 1024; i += 256) {
        int r = i >> 5, cc = i & 31;
        s1t[r][cc] = sp[((size_t)(b*Nn) + n0 + r) * Nn + m0 + cc];
        s2t[r][cc] = sp[((size_t)(b*Nn) + m0 + r) * Nn + n0 + cc];
        abt[r][cc] = ab[((size_t)(b*Nn) + n0 + r) * Nn + m0 + cc];
    }
    __syncthreads();
    for (int h = 0; h < H_; h++) {
        for (int i = tid; i < 1024; i += 256) {
            int r = i >> 5, cc = i & 31;
            float v = se[s1t[r][cc] * H_ + h] + ser[s2t[cc][r] * H_ + h] + abt[r][cc];
            bias[(((size_t)(b*H_ + h) * Nn) + n0 + r) * Nn + m0 + cc] = v;
        }
    }
}

// ==================== bf16x3 tensor-core GEMM (mma.sync + ldmatrix) ==========
#define RS   20
#define STG  30720
#define GSMT (3*STG)

#define GISSUE(t, s) do { \
    unsigned so_ = sb + (unsigned)(s)*STG; \
    unsigned da_ = so_ + arow*80u + ac0*16u; \
    const char* gah_ = Agh + (size_t)(t)*64 + ac0*16; \
    const char* gal_ = Agl + (size_t)(t)*64 + ac0*16; \
    CP_ASYNC16(da_, gah_); CP_ASYNC16(da_+16u, gah_+16); \
    CP_ASYNC16(da_+10240u, gal_); CP_ASYNC16(da_+10256u, gal_+16); \
    unsigned db_ = so_ + 20480u + brow*80u + bc*16u; \
    CP_ASYNC16(db_, Bgh + (size_t)(t)*64 + bc*16); \
    CP_ASYNC16(db_+5120u, Bgl + (size_t)(t)*64 + bc*16); \
} while (0)

template<int EPI>  // 0 = bias -> fp32 C;  1 = bias+gelu -> bf16 hi/lo Ch/Cl
__global__ void __launch_bounds__(256, 2)
mma_gemm(const __nv_bfloat16* __restrict__ Ah, const __nv_bfloat16* __restrict__ Al,
         const __nv_bfloat16* __restrict__ Wh, const __nv_bfloat16* __restrict__ Wl,
         const float* __restrict__ bias, float* __restrict__ C,
         __nv_bfloat16* __restrict__ Ch, __nv_bfloat16* __restrict__ Cl,
         int M, int K, int Nc, float scale) {
    extern __shared__ char sm[];
    unsigned sb = smem_u32(sm);
    int tid = threadIdx.x, wid = tid >> 5, lane = tid & 31;
    int q = lane & 3;
    int wm = (wid & 3) * 32, wn = (wid >> 2) * 32;
    int bm0 = blockIdx.y * 128, bn0 = blockIdx.x * 64;

    // cp.async producer mapping
    unsigned arow = tid >> 1;
    unsigned ac0  = (tid & 1) * 2;
    unsigned brow = tid >> 2;
    unsigned bc   = tid & 3;
    const char* Agh = (const char*)(Ah + (size_t)(bm0 + arow) * K);
    const char* Agl = (const char*)(Al + (size_t)(bm0 + arow) * K);
    const char* Bgh = (const char*)(Wh + (size_t)(bn0 + brow) * K);
    const char* Bgl = (const char*)(Wl + (size_t)(bn0 + brow) * K);

    // ldmatrix per-lane address offsets (relative to stage base)
    unsigned lsub = (unsigned)lane >> 3, lr = (unsigned)lane & 7;
    unsigned aoff = ((unsigned)wm + (lsub & 1) * 8 + lr) * 80u + (lsub >> 1) * 16u;
    unsigned boff = 20480u + ((unsigned)wn + (lsub >> 1) * 8 + lr) * 80u + (lsub & 1) * 16u;

    float acc[2][4][4];
#pragma unroll
    for (int i = 0; i < 2; i++)
#pragma unroll
        for (int j = 0; j < 4; j++)
#pragma unroll
            for (int c = 0; c < 4; c++) acc[i][j][c] = 0.f;

    int ntiles = K >> 5;
    GISSUE(0, 0); CP_COMMIT();
    GISSUE(1, 1); CP_COMMIT();

    for (int t = 0; t < ntiles; t++) {
        CP_WAIT1();
        __syncthreads();
        int tn = t + 2;
        if (tn < ntiles) { int s2 = tn % 3; GISSUE(tn, s2); }
        CP_COMMIT();

        unsigned stg = sb + (unsigned)(t % 3) * STG;
        unsigned aH = stg + aoff;            // A hi
        unsigned bH = stg + boff;            // B hi
#pragma unroll
        for (int kk = 0; kk < 2; kk++) {
            unsigned ko = (unsigned)kk * 32u;
            unsigned ah[2][4], al[2][4], bh[4][2], bl[4][2];
#pragma unroll
            for (int mt = 0; mt < 2; mt++) {
                unsigned a0 = aH + (unsigned)mt * 1280u + ko;
                LDMX4(ah[mt][0], ah[mt][1], ah[mt][2], ah[mt][3], a0);
                LDMX4(al[mt][0], al[mt][1], al[mt][2], al[mt][3], a0 + 10240u);
            }
#pragma unroll
            for (int np = 0; np < 2; np++) {
                unsigned b0 = bH + (unsigned)np * 1280u + ko;
                LDMX4(bh[2*np][0], bh[2*np][1], bh[2*np+1][0], bh[2*np+1][1], b0);
                LDMX4(bl[2*np][0], bl[2*np][1], bl[2*np+1][0], bl[2*np+1][1], b0 + 5120u);
            }
            // split-major issue: 8 independent acc chains per split term.
            // Per-acc contribution order stays hh -> lh -> hl (bitwise identical).
#pragma unroll
            for (int mt = 0; mt < 2; mt++)
#pragma unroll
                for (int nt = 0; nt < 4; nt++)
                    MMA_BF16(acc[mt][nt], ah[mt], bh[nt]);
#pragma unroll
            for (int mt = 0; mt < 2; mt++)
#pragma unroll
                for (int nt = 0; nt < 4; nt++)
                    MMA_BF16(acc[mt][nt], al[mt], bh[nt]);
#pragma unroll
            for (int mt = 0; mt < 2; mt++)
#pragma unroll
                for (int nt = 0; nt < 4; nt++)
                    MMA_BF16(acc[mt][nt], ah[mt], bl[nt]);
        }
    }

    int g = lane >> 2;
#pragma unroll
    for (int mt = 0; mt < 2; mt++) {
#pragma unroll
        for (int nt = 0; nt < 4; nt++) {
            int col = bn0 + wn + nt*8 + 2*q;
            int r0  = bm0 + wm + mt*16 + g;
            float blo = bias[col], bhi = bias[col + 1];
            float v00 = (acc[mt][nt][0] + blo) * scale;
            float v01 = (acc[mt][nt][1] + bhi) * scale;
            float v10 = (acc[mt][nt][2] + blo) * scale;
            float v11 = (acc[mt][nt][3] + bhi) * scale;
            if (EPI == 0) {
                *(float2*)&C[(size_t)r0       * Nc + col] = make_float2(v00, v01);
                *(float2*)&C[(size_t)(r0 + 8) * Nc + col] = make_float2(v10, v11);
            } else {
                v00 = gelu_f(v00); v01 = gelu_f(v01);
                v10 = gelu_f(v10); v11 = gelu_f(v11);
                __nv_bfloat16 h0, l0, h1, l1;
                split_bf(v00, h0, l0); split_bf(v01, h1, l1);
                { __nv_bfloat162 hp; hp.x = h0; hp.y = h1;
                  *(__nv_bfloat162*)&Ch[(size_t)r0 * Nc + col] = hp;
                  __nv_bfloat162 lp; lp.x = l0; lp.y = l1;
                  *(__nv_bfloat162*)&Cl[(size_t)r0 * Nc + col] = lp; }
                split_bf(v10, h0, l0); split_bf(v11, h1, l1);
                { __nv_bfloat162 hp; hp.x = h0; hp.y = h1;
                  *(__nv_bfloat162*)&Ch[(size_t)(r0 + 8) * Nc + col] = hp;
                  __nv_bfloat162 lp; lp.x = l0; lp.y = l1;
                  *(__nv_bfloat162*)&Cl[(size_t)(r0 + 8) * Nc + col] = lp; }
            }
        }
    }
}

// ==================== fused attention: scores+bias+mask+softmax+PV ===========
#define FA_KD   0
#define FA_VD   (24*385)
#define FA_QS   (2*24*385)
#define FA_MK   (2*24*385 + 384*25)
#define FA_SMEM ((2*24*385 + 384*25 + 384) * 4)

__global__ void __launch_bounds__(256, 1)
fattn_k(const float* __restrict__ qkv, const float* __restrict__ bias,
        const int* __restrict__ nt,
        __nv_bfloat16* __restrict__ oh, __nv_bfloat16* __restrict__ ol) {
    extern __shared__ float fs[];
    float* kd = fs + FA_KD;
    float* vd = fs + FA_VD;
    float* qs = fs + FA_QS;
    float* mk = fs + FA_MK;
    int bh = blockIdx.x;
    int b = bh >> 5, h = bh & 31;
    int tid = threadIdx.x, w = tid >> 5, lane = tid & 31;
    const float scaling = 0.20412414523193154f;   // 24^-0.5

    for (int i = tid; i < 384*24; i += 256) {
        int m = i / 24, d = i % 24;
        size_t base = ((size_t)m*B_ + b)*QKV + h*D_ + d;
        qs[m*25 + d]  = qkv[base] * scaling;
        kd[d*385 + m] = qkv[base + E_];
        vd[d*385 + m] = qkv[base + 2*E_];
    }
    for (int i = tid; i < 384; i += 256)
        mk[i] = (nt[b*Nn + i] == 0) ? -1e30f : 0.f;
    __syncthreads();

    for (int g = 0; g < 12; g++) {
        int r0 = g*32 + w*4;
        float sv[4][12];
#pragma unroll
        for (int r = 0; r < 4; r++)
#pragma unroll
            for (int j = 0; j < 12; j++) sv[r][j] = 0.f;

#pragma unroll
        for (int db = 0; db < 4; db++) {
            float qreg[4][6];
#pragma unroll
            for (int r = 0; r < 4; r++)
#pragma unroll
                for (int dd = 0; dd < 6; dd++)
                    qreg[r][dd] = qs[(r0 + r)*25 + db*6 + dd];
#pragma unroll
            for (int j = 0; j < 12; j++) {
                int m = lane + 32*j;
#pragma unroll
                for (int dd = 0; dd < 6; dd++) {
                    float kv = kd[(db*6 + dd)*385 + m];
#pragma unroll
                    for (int r = 0; r < 4; r++)
                        sv[r][j] = fmaf(qreg[r][dd], kv, sv[r][j]);
                }
            }
        }

#pragma unroll
        for (int r = 0; r < 4; r++) {
            int n = r0 + r;
            const float* brow = bias + ((size_t)bh*Nn + n)*Nn;
            float mx = -3.4e38f;
#pragma unroll
            for (int j = 0; j < 12; j++) {
                int m = lane + 32*j;
                float val = sv[r][j] + brow[m] + mk[m];
                sv[r][j] = val; mx = fmaxf(mx, val);
            }
            for (int o = 16; o; o >>= 1) mx = fmaxf(mx, __shfl_xor_sync(0xffffffffu, mx, o));
            float sum = 0.f;
#pragma unroll
            for (int j = 0; j < 12; j++) {
                float e = __expf(sv[r][j] - mx); sv[r][j] = e; sum += e;
            }
            for (int o = 16; o; o >>= 1) sum += __shfl_xor_sync(0xffffffffu, sum, o);
            float inv = 1.f / sum;
#pragma unroll
            for (int j = 0; j < 12; j++) sv[r][j] *= inv;
        }

        float acc[4][24];
#pragma unroll
        for (int r = 0; r < 4; r++)
#pragma unroll
            for (int d = 0; d < 24; d++) acc[r][d] = 0.f;
#pragma unroll
        for (int j = 0; j < 12; j++) {
            int m = lane + 32*j;
#pragma unroll
            for (int d = 0; d < 24; d++) {
                float v = vd[d*385 + m];
#pragma unroll
                for (int r = 0; r < 4; r++)
                    acc[r][d] = fmaf(sv[r][j], v, acc[r][d]);
            }
        }

#pragma unroll
        for (int r = 0; r < 4; r++) {
            int n = r0 + r;
            float myv = 0.f;
#pragma unroll
            for (int d = 0; d < 24; d++) {
                float t = acc[r][d];
                for (int o = 16; o; o >>= 1) t += __shfl_xor_sync(0xffffffffu, t, o);
                if (lane == d) myv = t;
            }
            if (lane < 24) {
                size_t idx = ((size_t)n*B_ + b)*E_ + h*D_ + lane;
                __nv_bfloat16 hv, lv; split_bf(myv, hv, lv);
                oh[idx] = hv; ol[idx] = lv;
            }
        }
    }
}

// ==================== residual add + LayerNorm (+ bf16 hi/lo out) ============
__global__ void __launch_bounds__(256)
ln_k(const float* __restrict__ x, const float* __restrict__ a,
     const float* __restrict__ s, const float* __restrict__ bb,
     float* __restrict__ out,
     __nv_bfloat16* __restrict__ oh, __nv_bfloat16* __restrict__ ol) {
    __shared__ float r1[8], r2[8];
    int t = blockIdx.x, tid = threadIdx.x;
    const float* xp = x + (size_t)t * E_;
    const float* ap = a + (size_t)t * E_;
    float v[3]; float sum = 0.f;
#pragma unroll
    for (int i = 0; i < 3; i++) { int e = tid + (i << 8); v[i] = xp[e] + ap[e]; sum += v[i]; }
    for (int o = 16; o; o >>= 1) sum += __shfl_xor_sync(0xffffffffu, sum, o);
    if ((tid & 31) == 0) r1[tid >> 5] = sum;
    __syncthreads();
    sum = 0.f;
#pragma unroll
    for (int w = 0; w < 8; w++) sum += r1[w];
    float mu = sum * (1.f / 768.f);
    float var = 0.f;
#pragma unroll
    for (int i = 0; i < 3; i++) { float d = v[i] - mu; var += d * d; }
    for (int o = 16; o; o >>= 1) var += __shfl_xor_sync(0xffffffffu, var, o);
    if ((tid & 31) == 0) r2[tid >> 5] = var;
    __syncthreads();
    var = 0.f;
#pragma unroll
    for (int w = 0; w < 8; w++) var += r2[w];
    float rstd = rsqrtf(var * (1.f / 768.f) + 1e-5f);
#pragma unroll
    for (int i = 0; i < 3; i++) {
        int e = tid + (i << 8);
        float o = (v[i] - mu) * rstd * s[e] + bb[e];
        out[(size_t)t * E_ + e] = o;
        __nv_bfloat16 hh, ll; split_bf(o, hh, ll);
        oh[(size_t)t * E_ + e] = hh; ol[(size_t)t * E_ + e] = ll;
    }
}

// ==================== orchestration ====================
extern "C" void kernel_launch(void* const* d_in, const int* in_sizes, int n_in,
                              void* d_out, int out_size) {
    const int*   nt    = (const int*)  d_in[0];
    const float* nif   = (const float*)d_in[1];
    const int*   ind   = (const int*)  d_in[2];
    const int*   outd  = (const int*)  d_in[3];
    const float* ab    = (const float*)d_in[4];
    const int*   sp    = (const int*)  d_in[5];
    const float* nemb  = (const float*)d_in[6];
    const float* iemb  = (const float*)d_in[7];
    const float* oemb  = (const float*)d_in[8];
    const float* se    = (const float*)d_in[9];
    const float* ser   = (const float*)d_in[10];
    const float* Wq    = (const float*)d_in[11];
    const float* bq    = (const float*)d_in[12];
    const float* Wk    = (const float*)d_in[13];
    const float* bk    = (const float*)d_in[14];
    const float* Wv    = (const float*)d_in[15];
    const float* bv    = (const float*)d_in[16];
    const float* Wo    = (const float*)d_in[17];
    const float* bo    = (const float*)d_in[18];
    const float* W1    = (const float*)d_in[19];
    const float* b1    = (const float*)d_in[20];
    const float* W2    = (const float*)d_in[21];
    const float* b2    = (const float*)d_in[22];
    const float* ln1s  = (const float*)d_in[23];
    const float* ln1b  = (const float*)d_in[24];
    const float* ln2s  = (const float*)d_in[25];
    const float* ln2b  = (const float*)d_in[26];
    float* out = (float*)d_out;

    float *x, *tmp, *qkv, *bias, *bqkv;
    __nv_bfloat16 *xh, *xl, *ch, *cl, *hh, *hl;
    __nv_bfloat16 *wqkvh, *wqkvl, *woh, *wol, *w1h, *w1l, *w2h, *w2l;
    cudaGetSymbolAddress((void**)&x,    g_x);
    cudaGetSymbolAddress((void**)&tmp,  g_tmp);
    cudaGetSymbolAddress((void**)&qkv,  g_qkv);
    cudaGetSymbolAddress((void**)&bias, g_bias);
    cudaGetSymbolAddress((void**)&bqkv, g_bqkv);
    cudaGetSymbolAddress((void**)&xh,   g_xh);
    cudaGetSymbolAddress((void**)&xl,   g_xl);
    cudaGetSymbolAddress((void**)&ch,   g_ch);
    cudaGetSymbolAddress((void**)&cl,   g_cl);
    cudaGetSymbolAddress((void**)&hh,   g_hh);
    cudaGetSymbolAddress((void**)&hl,   g_hl);
    cudaGetSymbolAddress((void**)&wqkvh, g_wqkvh);
    cudaGetSymbolAddress((void**)&wqkvl, g_wqkvl);
    cudaGetSymbolAddress((void**)&woh,   g_woh);
    cudaGetSymbolAddress((void**)&wol,   g_wol);
    cudaGetSymbolAddress((void**)&w1h,   g_w1h);
    cudaGetSymbolAddress((void**)&w1l,   g_w1l);
    cudaGetSymbolAddress((void**)&w2h,   g_w2h);
    cudaGetSymbolAddress((void**)&w2l,   g_w2l);

    cudaFuncSetAttribute(mma_gemm<0>, cudaFuncAttributeMaxDynamicSharedMemorySize, GSMT);
    cudaFuncSetAttribute(mma_gemm<1>, cudaFuncAttributeMaxDynamicSharedMemorySize, GSMT);
    cudaFuncSetAttribute(fattn_k, cudaFuncAttributeMaxDynamicSharedMemorySize, FA_SMEM);

    // ---- prepass: 5 launches, so launch idx 5 == first QKV GEMM (ncu -s 5) ----
    tr4_k<<<dim3(E_/32, E_/32, 4*L_), 256>>>(Wq, Wk, Wv, Wo,
                                             wqkvh, wqkvl, woh, wol);       // idx 0
    tr_k<<<dim3(F_/32, E_/32, L_), 256>>>(W1, w1h, w1l, E_, F_,
        (size_t)E_*F_, (size_t)F_*E_, 0);                                   // idx 1
    tr_k<<<dim3(E_/32, F_/32, L_), 256>>>(W2, w2h, w2l, F_, E_,
        (size_t)F_*E_, (size_t)E_*F_, 0);                                   // idx 2
    embed_packb_k<<<4608 + 108, 256>>>(nt, nif, ind, outd, nemb, iemb, oemb,
                                       x, xh, xl, bq, bk, bv, bqkv);        // idx 3
    bias_k<<<dim3(B_, Nn/32, Nn/32), 256>>>(sp, ab, se, ser, bias);         // idx 4

    dim3 gQKV(QKV/64, T_/128);     // (36, 12)
    dim3 gE(E_/64, T_/128);        // (12, 12)
    dim3 gF1(F_/64, T_/128);       // (48, 12)

    for (int l = 0; l < L_; l++) {
        mma_gemm<0><<<gQKV, 256, GSMT>>>(xh, xl,
            wqkvh + (size_t)l*QKV*E_, wqkvl + (size_t)l*QKV*E_,
            bqkv + l*QKV, qkv, hh, hl, T_, E_, QKV, 1.f);                   // idx 5 (l=0)

        fattn_k<<<B_*H_, 256, FA_SMEM>>>(qkv, bias, nt, ch, cl);

        mma_gemm<0><<<gE, 256, GSMT>>>(ch, cl,
            woh + (size_t)l*E_*E_, wol + (size_t)l*E_*E_,
            bo + l*E_, tmp, hh, hl, T_, E_, E_, 1.f);
        ln_k<<<T_, 256>>>(x, tmp, ln1s + l*E_, ln1b + l*E_, x, xh, xl);

        mma_gemm<1><<<gF1, 256, GSMT>>>(xh, xl,
            w1h + (size_t)l*F_*E_, w1l + (size_t)l*F_*E_,
            b1 + l*F_, tmp, hh, hl, T_, E_, F_, 1.f);
        mma_gemm<0><<<gE, 256, GSMT>>>(hh, hl,
            w2h + (size_t)l*E_*F_, w2l + (size_t)l*E_*F_,
            b2 + l*E_, tmp, hh, hl, T_, F_, E_, 1.f);

        float* dst = (l == L_-1) ? out : x;
        ln_k<<<T_, 256>>>(x, tmp, ln2s + l*E_, ln2b + l*E_, dst, xh, xl);
    }
}